// round 13
// baseline (speedup 1.0000x reference)
#include <cuda_runtime.h>
#include <cuda_bf16.h>
#include <math.h>
#include <stdint.h>
#include <stddef.h>

#define NN 65536
#define EE 1048576
#define FMAXV 3.402823466e38f

// ---------------- static device scratch (no allocations) ----------------
__device__ float g_e[(size_t)EE * 32];      // edge_attr @ W_edge^T
__device__ float g_c[(size_t)EE * 128];     // e @ Wpre_edgepart
__device__ float g_a[(size_t)NN * 128];     // dst-side node pre-part
__device__ float g_b[(size_t)NN * 128];     // src-side node pre-part
__device__ float g_agg[(size_t)NN * 512];   // per node/tower: [mean|mx|mn|std] x32
__device__ float g_Z[(size_t)NN * 128];     // post-MLP output
__device__ float g_s1[NN];
__device__ float g_s2[NN];
__device__ int   g_cnt[NN];
__device__ int   g_fill[NN];
__device__ int   g_rowptr[NN + 1];
__device__ int   g_eid[EE];
__device__ int   g_bsum[256];
__device__ float g_biasm[128];
__device__ float g_WedgeT[128 * 32];        // [k][f]
__device__ float g_WlinT[128 * 128];        // [k][c]
__device__ float g_avglog;

// ---------------- tf32 mma helpers ----------------
__device__ __forceinline__ unsigned f2tf(float x) {
    unsigned r;
    asm("cvt.rna.tf32.f32 %0, %1;" : "=r"(r) : "f"(x));
    return r;
}
__device__ __forceinline__ void mma_tf32(float& d0, float& d1, float& d2, float& d3,
                                         unsigned a0, unsigned a1, unsigned a2, unsigned a3,
                                         unsigned b0, unsigned b1) {
    asm("mma.sync.aligned.m16n8k8.row.col.f32.tf32.tf32.f32 "
        "{%0,%1,%2,%3},{%4,%5,%6,%7},{%8,%9},{%0,%1,%2,%3};"
        : "+f"(d0), "+f"(d1), "+f"(d2), "+f"(d3)
        : "r"(a0), "r"(a1), "r"(a2), "r"(a3), "r"(b0), "r"(b1));
}

// ---------------- setup ----------------
__global__ void k_zero(void) {
    int i = blockIdx.x * 256 + threadIdx.x;
    if (i < NN) { g_cnt[i] = 0; g_fill[i] = 0; }
}

__global__ void k_prep(const float* __restrict__ W_edge, const float* __restrict__ W_lin,
                       const float* __restrict__ W_pre, const float* __restrict__ b_pre,
                       const float* __restrict__ b_edge) {
    int i = blockIdx.x * 256 + threadIdx.x;
    if (i < 128 * 32) {
        int k = i >> 5, f = i & 31;
        g_WedgeT[i] = W_edge[f * 128 + k];
    }
    if (i < 128 * 128) {
        int k = i >> 7, c = i & 127;
        g_WlinT[i] = W_lin[c * 128 + k];
    }
    if (i < 128) {
        int t = i >> 5, g = i & 31;
        float s = b_pre[i];
        for (int j = 0; j < 32; j++)
            s += b_edge[j] * W_pre[t * 3072 + (64 + j) * 32 + g];
        g_biasm[i] = s;
    }
    if (i == 0) {
        const double cnts[6] = {108477.0, 299931.0, 180702.0, 10767.0, 3.0, 2.0};
        double num = 0.0, den = 0.0;
        for (int d = 0; d < 6; d++) { num += cnts[d] * log((double)(d + 1) + 1.0); den += cnts[d]; }
        g_avglog = (float)(num / den);
    }
}

// ---------------- CSR build ----------------
__global__ void k_hist(const int* __restrict__ dst) {
    int i = blockIdx.x * 256 + threadIdx.x;
    if (i < EE) atomicAdd(&g_cnt[dst[i]], 1);
}

__global__ void k_scan1(void) {
    int b = blockIdx.x, t = threadIdx.x;
    int gi = b * 256 + t;
    int v = g_cnt[gi];
    int lane = t & 31, w = t >> 5;
    int incl = v;
#pragma unroll
    for (int off = 1; off < 32; off <<= 1) {
        int u = __shfl_up_sync(0xffffffffu, incl, off);
        if (lane >= off) incl += u;
    }
    __shared__ int wtot[8];
    __shared__ int woff[8];
    if (lane == 31) wtot[w] = incl;
    __syncthreads();
    if (t == 0) {
        int run = 0;
        for (int i = 0; i < 8; i++) { woff[i] = run; run += wtot[i]; }
        g_bsum[b] = run;
    }
    __syncthreads();
    g_rowptr[gi] = woff[w] + incl - v;
}

__global__ void k_scan2(void) {
    int t = threadIdx.x;
    int v = g_bsum[t];
    int lane = t & 31, w = t >> 5;
    int incl = v;
#pragma unroll
    for (int off = 1; off < 32; off <<= 1) {
        int u = __shfl_up_sync(0xffffffffu, incl, off);
        if (lane >= off) incl += u;
    }
    __shared__ int wtot[8];
    __shared__ int woff[8];
    if (lane == 31) wtot[w] = incl;
    __syncthreads();
    if (t == 0) {
        int run = 0;
        for (int i = 0; i < 8; i++) { woff[i] = run; run += wtot[i]; }
    }
    __syncthreads();
    g_bsum[t] = woff[w] + incl - v;
    if (t == 0) g_rowptr[NN] = EE;
}

__global__ void k_scan3(void) {
    int b = blockIdx.x, t = threadIdx.x;
    g_rowptr[b * 256 + t] += g_bsum[b];
}

__global__ void k_scatter(const int* __restrict__ dst) {
    int i = blockIdx.x * 256 + threadIdx.x;
    if (i < EE) {
        int d = dst[i];
        int slot = g_rowptr[d] + atomicAdd(&g_fill[d], 1);
        g_eid[slot] = i;
    }
}

// ---------------- node pre-parts: smem weights + vectorized broadcast x ----------------
__global__ __launch_bounds__(256) void k_ab(const float* __restrict__ x,
                                            const float* __restrict__ W_pre) {
    __shared__ float sW[4 * 64 * 32];   // 32KB: [t][row 0..63][g]; rows 0..31 = a, 32..63 = b
    int tid = threadIdx.x;
    for (int i = tid; i < 4 * 64 * 32; i += 256) {
        int t = i >> 11, rem = i & 2047;
        sW[i] = W_pre[t * 3072 + rem];
    }
    __syncthreads();

    int gi = blockIdx.x * 256 + tid;     // (n, ch) flat index
    int n = gi >> 7, ch = gi & 127;
    int t = ch >> 5, g = ch & 31;

    const float4* xr = (const float4*)(x + (size_t)n * 128 + t * 32);
    float xv[32];
#pragma unroll
    for (int q = 0; q < 8; q++) {
        float4 v = __ldg(&xr[q]);
        xv[q * 4 + 0] = v.x; xv[q * 4 + 1] = v.y;
        xv[q * 4 + 2] = v.z; xv[q * 4 + 3] = v.w;
    }
    const float* wa = &sW[t * 2048 + g];
    float a = 0.f, b = 0.f;
#pragma unroll
    for (int f = 0; f < 32; f++) {
        a = fmaf(xv[f], wa[f * 32], a);
        b = fmaf(xv[f], wa[1024 + f * 32], b);
    }
    g_a[gi] = a; g_b[gi] = b;
}

// ---------------- e-GEMM (tf32 mma): e[E,32] = ea[E,128] @ WedgeT ----------------
__global__ __launch_bounds__(256) void k_egemm(const float* __restrict__ ea) {
    __shared__ unsigned sA[256 * 36];
    __shared__ uint2    sB[4 * 4 * 32];
    int r0b = blockIdx.x * 256;
    int tid = threadIdx.x;
    int wid = tid >> 5, lane = tid & 31;
    int gid = lane >> 2, tig = lane & 3;
    int m0 = wid * 32;

    float acc[2][4][4];
#pragma unroll
    for (int mt = 0; mt < 2; mt++)
#pragma unroll
        for (int nt = 0; nt < 4; nt++)
#pragma unroll
            for (int q = 0; q < 4; q++) acc[mt][nt][q] = 0.f;

    for (int k0 = 0; k0 < 128; k0 += 32) {
        __syncthreads();
        for (int i = tid; i < 256 * 8; i += 256) {
            int r = i >> 3, kg = (i & 7) * 4;
            float4 v = *(const float4*)&ea[(size_t)(r0b + r) * 128 + k0 + kg];
            *(uint4*)&sA[r * 36 + kg] = make_uint4(f2tf(v.x), f2tf(v.y), f2tf(v.z), f2tf(v.w));
        }
        for (int i = tid; i < 512; i += 256) {
            int l = i & 31, nt = (i >> 5) & 3, ks = i >> 7;
            int tg = l & 3, gd = l >> 2;
            int rk = k0 + ks * 8 + tg;
            int cn = nt * 8 + gd;
            sB[i] = make_uint2(f2tf(g_WedgeT[rk * 32 + cn]),
                               f2tf(g_WedgeT[(rk + 4) * 32 + cn]));
        }
        __syncthreads();
#pragma unroll
        for (int ks = 0; ks < 4; ks++) {
#pragma unroll
            for (int mt = 0; mt < 2; mt++) {
                int base = m0 + mt * 16;
                unsigned a0 = sA[(base + gid) * 36 + ks * 8 + tig];
                unsigned a1 = sA[(base + gid + 8) * 36 + ks * 8 + tig];
                unsigned a2 = sA[(base + gid) * 36 + ks * 8 + tig + 4];
                unsigned a3 = sA[(base + gid + 8) * 36 + ks * 8 + tig + 4];
#pragma unroll
                for (int nt = 0; nt < 4; nt++) {
                    uint2 b = sB[(ks * 4 + nt) * 32 + lane];
                    mma_tf32(acc[mt][nt][0], acc[mt][nt][1], acc[mt][nt][2], acc[mt][nt][3],
                             a0, a1, a2, a3, b.x, b.y);
                }
            }
        }
    }
#pragma unroll
    for (int mt = 0; mt < 2; mt++) {
        int base = r0b + m0 + mt * 16;
#pragma unroll
        for (int nt = 0; nt < 4; nt++) {
            int col = nt * 8 + tig * 2;
            *(float2*)&g_e[(size_t)(base + gid) * 32 + col] =
                make_float2(acc[mt][nt][0], acc[mt][nt][1]);
            *(float2*)&g_e[(size_t)(base + gid + 8) * 32 + col] =
                make_float2(acc[mt][nt][2], acc[mt][nt][3]);
        }
    }
}

// ---------------- c-GEMM (tf32 mma): c[E,128] = e[E,32] @ Wpre_e ----------------
__global__ __launch_bounds__(256) void k_cgemm(const float* __restrict__ W_pre) {
    __shared__ unsigned sE[128 * 36];
    __shared__ uint2    sB[4 * 16 * 32];
    int r0b = blockIdx.x * 128;
    int tid = threadIdx.x;
    int wid = tid >> 5, lane = tid & 31;
    int gid = lane >> 2, tig = lane & 3;
    int m0 = wid * 16;

    for (int i = tid; i < 128 * 8; i += 256) {
        int r = i >> 3, kg = (i & 7) * 4;
        float4 v = *(const float4*)&g_e[(size_t)(r0b + r) * 32 + kg];
        *(uint4*)&sE[r * 36 + kg] = make_uint4(f2tf(v.x), f2tf(v.y), f2tf(v.z), f2tf(v.w));
    }
    for (int i = tid; i < 2048; i += 256) {
        int l = i & 31, nt = (i >> 5) & 15, ks = i >> 9;
        int tg = l & 3, gd = l >> 2;
        int j = ks * 8 + tg;
        int o = nt * 8 + gd;
        int t = o >> 5, g = o & 31;
        sB[i] = make_uint2(f2tf(W_pre[t * 3072 + (64 + j) * 32 + g]),
                           f2tf(W_pre[t * 3072 + (64 + j + 4) * 32 + g]));
    }
    __syncthreads();

    float acc[16][4];
#pragma unroll
    for (int nt = 0; nt < 16; nt++)
#pragma unroll
        for (int q = 0; q < 4; q++) acc[nt][q] = 0.f;

#pragma unroll
    for (int ks = 0; ks < 4; ks++) {
        unsigned a0 = sE[(m0 + gid) * 36 + ks * 8 + tig];
        unsigned a1 = sE[(m0 + gid + 8) * 36 + ks * 8 + tig];
        unsigned a2 = sE[(m0 + gid) * 36 + ks * 8 + tig + 4];
        unsigned a3 = sE[(m0 + gid + 8) * 36 + ks * 8 + tig + 4];
#pragma unroll
        for (int nt = 0; nt < 16; nt++) {
            uint2 b = sB[(ks * 16 + nt) * 32 + lane];
            mma_tf32(acc[nt][0], acc[nt][1], acc[nt][2], acc[nt][3],
                     a0, a1, a2, a3, b.x, b.y);
        }
    }
    int base = r0b + m0;
#pragma unroll
    for (int nt = 0; nt < 16; nt++) {
        int col = nt * 8 + tig * 2;
        *(float2*)&g_c[(size_t)(base + gid) * 128 + col] = make_float2(acc[nt][0], acc[nt][1]);
        *(float2*)&g_c[(size_t)(base + gid + 8) * 128 + col] = make_float2(acc[nt][2], acc[nt][3]);
    }
}

// ---------------- aggregation: one warp per node (sorted edge list, 2-edge ILP) ----------------
__global__ __launch_bounds__(256) void k_agg(const int* __restrict__ srcp) {
    __shared__ int s_eid[8][128];
    int w = threadIdx.x >> 5;
    int lane = threadIdx.x & 31;
    int n = blockIdx.x * 8 + w;
    if (n >= NN) return;
    int start = g_rowptr[n], end = g_rowptr[n + 1];
    int deg = end - start;
    int msort = deg < 128 ? deg : 128;

    for (int j = lane; j < msort; j += 32) s_eid[w][j] = g_eid[start + j];
    __syncwarp();
    for (int pass = 0; pass < msort; pass++) {
        int off = pass & 1;
        for (int j = lane; 2 * j + 1 + off < msort; j += 32) {
            int i0 = 2 * j + off, i1 = i0 + 1;
            int a = s_eid[w][i0], b = s_eid[w][i1];
            if (a > b) { s_eid[w][i0] = b; s_eid[w][i1] = a; }
        }
        __syncwarp();
    }

    float4 base = *(const float4*)&g_a[(size_t)n * 128 + lane * 4];
    float4 bm   = *(const float4*)&g_biasm[lane * 4];
    base.x += bm.x; base.y += bm.y; base.z += bm.z; base.w += bm.w;

    float4 s  = make_float4(0.f, 0.f, 0.f, 0.f);
    float4 sq = make_float4(0.f, 0.f, 0.f, 0.f);
    float4 mx = make_float4(-FMAXV, -FMAXV, -FMAXV, -FMAXV);
    float4 mn = make_float4( FMAXV,  FMAXV,  FMAXV,  FMAXV);

    int sl = 0;
    for (; sl + 2 <= deg; sl += 2) {
        int eid0 = (sl     < 128) ? s_eid[w][sl]     : __ldg(&g_eid[start + sl]);
        int eid1 = (sl + 1 < 128) ? s_eid[w][sl + 1] : __ldg(&g_eid[start + sl + 1]);
        int sn0 = __ldg(&srcp[eid0]);
        int sn1 = __ldg(&srcp[eid1]);
        float4 c0 = *(const float4*)&g_c[(size_t)eid0 * 128 + lane * 4];
        float4 b0 = *(const float4*)&g_b[(size_t)sn0 * 128 + lane * 4];
        float4 c1 = *(const float4*)&g_c[(size_t)eid1 * 128 + lane * 4];
        float4 b1 = *(const float4*)&g_b[(size_t)sn1 * 128 + lane * 4];

        float m0 = base.x + b0.x + c0.x;
        float m1 = base.y + b0.y + c0.y;
        float m2 = base.z + b0.z + c0.z;
        float m3 = base.w + b0.w + c0.w;
        s.x += m0; s.y += m1; s.z += m2; s.w += m3;
        sq.x = fmaf(m0, m0, sq.x); sq.y = fmaf(m1, m1, sq.y);
        sq.z = fmaf(m2, m2, sq.z); sq.w = fmaf(m3, m3, sq.w);
        mx.x = fmaxf(mx.x, m0); mx.y = fmaxf(mx.y, m1); mx.z = fmaxf(mx.z, m2); mx.w = fmaxf(mx.w, m3);
        mn.x = fminf(mn.x, m0); mn.y = fminf(mn.y, m1); mn.z = fminf(mn.z, m2); mn.w = fminf(mn.w, m3);

        float p0 = base.x + b1.x + c1.x;
        float p1 = base.y + b1.y + c1.y;
        float p2 = base.z + b1.z + c1.z;
        float p3 = base.w + b1.w + c1.w;
        s.x += p0; s.y += p1; s.z += p2; s.w += p3;
        sq.x = fmaf(p0, p0, sq.x); sq.y = fmaf(p1, p1, sq.y);
        sq.z = fmaf(p2, p2, sq.z); sq.w = fmaf(p3, p3, sq.w);
        mx.x = fmaxf(mx.x, p0); mx.y = fmaxf(mx.y, p1); mx.z = fmaxf(mx.z, p2); mx.w = fmaxf(mx.w, p3);
        mn.x = fminf(mn.x, p0); mn.y = fminf(mn.y, p1); mn.z = fminf(mn.z, p2); mn.w = fminf(mn.w, p3);
    }
    for (; sl < deg; sl++) {
        int eid = (sl < 128) ? s_eid[w][sl] : __ldg(&g_eid[start + sl]);
        int sn  = __ldg(&srcp[eid]);
        float4 c = *(const float4*)&g_c[(size_t)eid * 128 + lane * 4];
        float4 b = *(const float4*)&g_b[(size_t)sn * 128 + lane * 4];
        float m0 = base.x + b.x + c.x;
        float m1 = base.y + b.y + c.y;
        float m2 = base.z + b.z + c.z;
        float m3 = base.w + b.w + c.w;
        s.x += m0; s.y += m1; s.z += m2; s.w += m3;
        sq.x = fmaf(m0, m0, sq.x); sq.y = fmaf(m1, m1, sq.y);
        sq.z = fmaf(m2, m2, sq.z); sq.w = fmaf(m3, m3, sq.w);
        mx.x = fmaxf(mx.x, m0); mx.y = fmaxf(mx.y, m1); mx.z = fmaxf(mx.z, m2); mx.w = fmaxf(mx.w, m3);
        mn.x = fminf(mn.x, m0); mn.y = fminf(mn.y, m1); mn.z = fminf(mn.z, m2); mn.w = fminf(mn.w, m3);
    }
    if (deg == 0) {
        mx = make_float4(0.f, 0.f, 0.f, 0.f);
        mn = make_float4(0.f, 0.f, 0.f, 0.f);
    }
    float cs = (float)(deg > 0 ? deg : 1);
    float inv = 1.0f / cs;
    float4 mean = make_float4(s.x * inv, s.y * inv, s.z * inv, s.w * inv);
    float4 msq  = make_float4(sq.x * inv, sq.y * inv, sq.z * inv, sq.w * inv);
    float4 sd;
    sd.x = sqrtf(fmaxf(msq.x - mean.x * mean.x, 0.f) + 1e-5f);
    sd.y = sqrtf(fmaxf(msq.y - mean.y * mean.y, 0.f) + 1e-5f);
    sd.z = sqrtf(fmaxf(msq.z - mean.z * mean.z, 0.f) + 1e-5f);
    sd.w = sqrtf(fmaxf(msq.w - mean.w * mean.w, 0.f) + 1e-5f);

    int t = (lane * 4) >> 5, g0 = (lane * 4) & 31;
    float* aggp = &g_agg[(size_t)n * 512 + t * 128 + g0];
    *(float4*)&aggp[0]  = mean;
    *(float4*)&aggp[32] = mx;
    *(float4*)&aggp[64] = mn;
    *(float4*)&aggp[96] = sd;

    if (lane == 0) {
        float avg = g_avglog;
        float logd = logf((float)deg + 1.0f);
        g_s1[n] = logd / avg;
        g_s2[n] = (deg == 0) ? 1.0f : (avg / logd);
    }
}

// ---------------- post-MLP (tf32 mma) ----------------
__global__ __launch_bounds__(256) void k_post(const float* __restrict__ x,
                                              const float* __restrict__ W_post,
                                              const float* __restrict__ b_post) {
    __shared__ unsigned sA[64 * 36];
    __shared__ uint2    sB0[4 * 4 * 32];
    __shared__ uint2    sB1[4 * 4 * 32];
    __shared__ uint2    sB2[4 * 4 * 32];
    __shared__ uint2    sB3[4 * 4 * 32];
    __shared__ float    s_c1[64], s_c2[64];

    int t  = blockIdx.y;
    int n0 = blockIdx.x * 64;
    int tid = threadIdx.x;
    int wid = tid >> 5, lane = tid & 31;
    int gid = lane >> 2, tig = lane & 3;
    int mt = wid >> 1, nh = wid & 1;
    int m0 = mt * 16;
    const float* Wt = W_post + (size_t)t * 416 * 32;

    for (int i = tid; i < 64 * 8; i += 256) {
        int r = i >> 3, fg = (i & 7) * 4;
        float4 v = *(const float4*)&x[(size_t)(n0 + r) * 128 + t * 32 + fg];
        *(uint4*)&sA[r * 36 + fg] = make_uint4(f2tf(v.x), f2tf(v.y), f2tf(v.z), f2tf(v.w));
    }
    for (int i = tid; i < 512; i += 256) {
        int l = i & 31, nt = (i >> 5) & 3, ks = i >> 7;
        int tg = l & 3, gd = l >> 2;
        int rk = ks * 8 + tg, cn = nt * 8 + gd;
        sB0[i] = make_uint2(f2tf(Wt[rk * 32 + cn]), f2tf(Wt[(rk + 4) * 32 + cn]));
    }
    if (tid < 64) { s_c1[tid] = g_s1[n0 + tid]; s_c2[tid] = g_s2[n0 + tid]; }
    __syncthreads();

    float acc1[2][4], acc2[2][4], acc3[2][4];
#pragma unroll
    for (int nl = 0; nl < 2; nl++)
#pragma unroll
        for (int q = 0; q < 4; q++) { acc1[nl][q] = 0.f; acc2[nl][q] = 0.f; acc3[nl][q] = 0.f; }

#pragma unroll
    for (int ks = 0; ks < 4; ks++) {
        unsigned a0 = sA[(m0 + gid) * 36 + ks * 8 + tig];
        unsigned a1 = sA[(m0 + gid + 8) * 36 + ks * 8 + tig];
        unsigned a2 = sA[(m0 + gid) * 36 + ks * 8 + tig + 4];
        unsigned a3 = sA[(m0 + gid + 8) * 36 + ks * 8 + tig + 4];
#pragma unroll
        for (int nl = 0; nl < 2; nl++) {
            int nt = nh * 2 + nl;
            uint2 b = sB0[(ks * 4 + nt) * 32 + lane];
            mma_tf32(acc1[nl][0], acc1[nl][1], acc1[nl][2], acc1[nl][3],
                     a0, a1, a2, a3, b.x, b.y);
        }
    }

    for (int kt = 0; kt < 4; kt++) {
        int k0 = kt * 32;
        __syncthreads();
        for (int i = tid; i < 64 * 8; i += 256) {
            int r = i >> 3, kg = (i & 7) * 4;
            float4 v = *(const float4*)&g_agg[(size_t)(n0 + r) * 512 + t * 128 + k0 + kg];
            *(uint4*)&sA[r * 36 + kg] = make_uint4(f2tf(v.x), f2tf(v.y), f2tf(v.z), f2tf(v.w));
        }
        for (int i = tid; i < 512; i += 256) {
            int l = i & 31, nt = (i >> 5) & 3, ks = i >> 7;
            int tg = l & 3, gd = l >> 2;
            int rk = k0 + ks * 8 + tg, cn = nt * 8 + gd;
            sB1[i] = make_uint2(f2tf(Wt[(32 + rk) * 32 + cn]),  f2tf(Wt[(32 + rk + 4) * 32 + cn]));
            sB2[i] = make_uint2(f2tf(Wt[(160 + rk) * 32 + cn]), f2tf(Wt[(160 + rk + 4) * 32 + cn]));
            sB3[i] = make_uint2(f2tf(Wt[(288 + rk) * 32 + cn]), f2tf(Wt[(288 + rk + 4) * 32 + cn]));
        }
        __syncthreads();
#pragma unroll
        for (int ks = 0; ks < 4; ks++) {
            unsigned a0 = sA[(m0 + gid) * 36 + ks * 8 + tig];
            unsigned a1 = sA[(m0 + gid + 8) * 36 + ks * 8 + tig];
            unsigned a2 = sA[(m0 + gid) * 36 + ks * 8 + tig + 4];
            unsigned a3 = sA[(m0 + gid + 8) * 36 + ks * 8 + tig + 4];
#pragma unroll
            for (int nl = 0; nl < 2; nl++) {
                int nt = nh * 2 + nl;
                uint2 b1 = sB1[(ks * 4 + nt) * 32 + lane];
                uint2 b2 = sB2[(ks * 4 + nt) * 32 + lane];
                uint2 b3 = sB3[(ks * 4 + nt) * 32 + lane];
                mma_tf32(acc1[nl][0], acc1[nl][1], acc1[nl][2], acc1[nl][3],
                         a0, a1, a2, a3, b1.x, b1.y);
                mma_tf32(acc2[nl][0], acc2[nl][1], acc2[nl][2], acc2[nl][3],
                         a0, a1, a2, a3, b2.x, b2.y);
                mma_tf32(acc3[nl][0], acc3[nl][1], acc3[nl][2], acc3[nl][3],
                         a0, a1, a2, a3, b3.x, b3.y);
            }
        }
    }

#pragma unroll
    for (int nl = 0; nl < 2; nl++) {
        int nt = nh * 2 + nl;
        int col = nt * 8 + tig * 2;
        float bp0 = b_post[t * 32 + col];
        float bp1 = b_post[t * 32 + col + 1];
        int r0 = m0 + gid;
        float c1a = s_c1[r0], c2a = s_c2[r0];
        float y00 = acc1[nl][0] + c1a * acc2[nl][0] + c2a * acc3[nl][0] + bp0;
        float y01 = acc1[nl][1] + c1a * acc2[nl][1] + c2a * acc3[nl][1] + bp1;
        *(float2*)&g_Z[(size_t)(n0 + r0) * 128 + t * 32 + col] = make_float2(y00, y01);
        int r1 = m0 + gid + 8;
        float c1b = s_c1[r1], c2b = s_c2[r1];
        float y10 = acc1[nl][2] + c1b * acc2[nl][2] + c2b * acc3[nl][2] + bp0;
        float y11 = acc1[nl][3] + c1b * acc2[nl][3] + c2b * acc3[nl][3] + bp1;
        *(float2*)&g_Z[(size_t)(n0 + r1) * 128 + t * 32 + col] = make_float2(y10, y11);
    }
}

// ---------------- final (tf32 mma): out = Z @ W_lin^T + b_lin + x ----------------
__global__ __launch_bounds__(256) void k_final(const float* __restrict__ x,
                                               const float* __restrict__ b_lin,
                                               float* __restrict__ out) {
    __shared__ unsigned sA[128 * 36];
    __shared__ uint2    sB[4 * 16 * 32];
    int r0b = blockIdx.x * 128;
    int tid = threadIdx.x;
    int wid = tid >> 5, lane = tid & 31;
    int gid = lane >> 2, tig = lane & 3;
    int m0 = wid * 16;

    float acc[16][4];
#pragma unroll
    for (int nt = 0; nt < 16; nt++)
#pragma unroll
        for (int q = 0; q < 4; q++) acc[nt][q] = 0.f;

    for (int k0 = 0; k0 < 128; k0 += 32) {
        __syncthreads();
        for (int i = tid; i < 128 * 8; i += 256) {
            int r = i >> 3, kg = (i & 7) * 4;
            float4 v = *(const float4*)&g_Z[(size_t)(r0b + r) * 128 + k0 + kg];
            *(uint4*)&sA[r * 36 + kg] = make_uint4(f2tf(v.x), f2tf(v.y), f2tf(v.z), f2tf(v.w));
        }
        for (int i = tid; i < 2048; i += 256) {
            int l = i & 31, nt = (i >> 5) & 15, ks = i >> 9;
            int tg = l & 3, gd = l >> 2;
            int rk = k0 + ks * 8 + tg, cn = nt * 8 + gd;
            sB[i] = make_uint2(f2tf(g_WlinT[rk * 128 + cn]),
                               f2tf(g_WlinT[(rk + 4) * 128 + cn]));
        }
        __syncthreads();
#pragma unroll
        for (int ks = 0; ks < 4; ks++) {
            unsigned a0 = sA[(m0 + gid) * 36 + ks * 8 + tig];
            unsigned a1 = sA[(m0 + gid + 8) * 36 + ks * 8 + tig];
            unsigned a2 = sA[(m0 + gid) * 36 + ks * 8 + tig + 4];
            unsigned a3 = sA[(m0 + gid + 8) * 36 + ks * 8 + tig + 4];
#pragma unroll
            for (int nt = 0; nt < 16; nt++) {
                uint2 b = sB[(ks * 16 + nt) * 32 + lane];
                mma_tf32(acc[nt][0], acc[nt][1], acc[nt][2], acc[nt][3],
                         a0, a1, a2, a3, b.x, b.y);
            }
        }
    }
    int base = r0b + m0;
#pragma unroll
    for (int nt = 0; nt < 16; nt++) {
        int col = nt * 8 + tig * 2;
        float2 bl = *(const float2*)&b_lin[col];
        float2 x0 = *(const float2*)&x[(size_t)(base + gid) * 128 + col];
        float2 x1 = *(const float2*)&x[(size_t)(base + gid + 8) * 128 + col];
        *(float2*)&out[(size_t)(base + gid) * 128 + col] =
            make_float2(acc[nt][0] + bl.x + x0.x, acc[nt][1] + bl.y + x0.y);
        *(float2*)&out[(size_t)(base + gid + 8) * 128 + col] =
            make_float2(acc[nt][2] + bl.x + x1.x, acc[nt][3] + bl.y + x1.y);
    }
}

// ---------------- launch (egemm moved to profiled slot #4) ----------------
extern "C" void kernel_launch(void* const* d_in, const int* in_sizes, int n_in,
                              void* d_out, int out_size) {
    const float* x         = (const float*)d_in[0];
    const float* edge_attr = (const float*)d_in[1];
    const int*   edge_idx  = (const int*)d_in[2];
    const float* W_edge    = (const float*)d_in[3];
    const float* b_edge    = (const float*)d_in[4];
    const float* W_pre     = (const float*)d_in[5];
    const float* b_pre     = (const float*)d_in[6];
    const float* W_post    = (const float*)d_in[7];
    const float* b_post    = (const float*)d_in[8];
    const float* W_lin     = (const float*)d_in[9];
    const float* b_lin     = (const float*)d_in[10];
    float* out = (float*)d_out;

    const int* srcp = edge_idx;
    const int* dstp = edge_idx + EE;

    k_zero<<<NN / 256, 256>>>();
    k_prep<<<64, 256>>>(W_edge, W_lin, W_pre, b_pre, b_edge);
    k_hist<<<EE / 256, 256>>>(dstp);
    k_egemm<<<EE / 256, 256>>>(edge_attr);       // profiled slot
    k_scan1<<<256, 256>>>();
    k_scan2<<<1, 256>>>();
    k_scan3<<<256, 256>>>();
    k_scatter<<<EE / 256, 256>>>(dstp);
    k_ab<<<(NN * 128) / 256, 256>>>(x, W_pre);
    k_cgemm<<<EE / 128, 256>>>(W_pre);
    k_agg<<<NN / 8, 256>>>(srcp);
    k_post<<<dim3(NN / 64, 4), 256>>>(x, W_post, b_post);
    k_final<<<NN / 128, 256>>>(x, b_lin, out);
}

// round 14
// speedup vs baseline: 1.1100x; 1.1100x over previous
#include <cuda_runtime.h>
#include <cuda_bf16.h>
#include <math.h>
#include <stdint.h>
#include <stddef.h>

#define NN 65536
#define EE 1048576
#define FMAXV 3.402823466e38f

// ---------------- static device scratch (no allocations) ----------------
__device__ float g_e[(size_t)EE * 32];      // edge_attr @ W_edge^T
__device__ float g_c[(size_t)EE * 128];     // e @ Wpre_edgepart
__device__ float g_a[(size_t)NN * 128];     // dst-side node pre-part
__device__ float g_b[(size_t)NN * 128];     // src-side node pre-part
__device__ float g_agg[(size_t)NN * 512];   // per node/tower: [mean|mx|mn|std] x32
__device__ float g_Z[(size_t)NN * 128];     // post-MLP output
__device__ float g_s1[NN];
__device__ float g_s2[NN];
__device__ int   g_cnt[NN];
__device__ int   g_fill[NN];
__device__ int   g_rowptr[NN + 1];
__device__ int   g_eid[EE];
__device__ int   g_bsum[256];
__device__ float g_biasm[128];
__device__ float g_WedgeT[128 * 32];        // [k][f]
__device__ float g_WlinT[128 * 128];        // [k][c]
__device__ float g_avglog;

// ---------------- tf32 mma helpers ----------------
__device__ __forceinline__ unsigned f2tf(float x) {
    unsigned r;
    asm("cvt.rna.tf32.f32 %0, %1;" : "=r"(r) : "f"(x));
    return r;
}
__device__ __forceinline__ void mma_tf32(float& d0, float& d1, float& d2, float& d3,
                                         unsigned a0, unsigned a1, unsigned a2, unsigned a3,
                                         unsigned b0, unsigned b1) {
    asm("mma.sync.aligned.m16n8k8.row.col.f32.tf32.tf32.f32 "
        "{%0,%1,%2,%3},{%4,%5,%6,%7},{%8,%9},{%0,%1,%2,%3};"
        : "+f"(d0), "+f"(d1), "+f"(d2), "+f"(d3)
        : "r"(a0), "r"(a1), "r"(a2), "r"(a3), "r"(b0), "r"(b1));
}

// ---------------- setup ----------------
__global__ void k_zero(void) {
    int i = blockIdx.x * 256 + threadIdx.x;
    if (i < NN) { g_cnt[i] = 0; g_fill[i] = 0; }
}

__global__ void k_prep(const float* __restrict__ W_edge, const float* __restrict__ W_lin,
                       const float* __restrict__ W_pre, const float* __restrict__ b_pre,
                       const float* __restrict__ b_edge) {
    int i = blockIdx.x * 256 + threadIdx.x;
    if (i < 128 * 32) {
        int k = i >> 5, f = i & 31;
        g_WedgeT[i] = W_edge[f * 128 + k];
    }
    if (i < 128 * 128) {
        int k = i >> 7, c = i & 127;
        g_WlinT[i] = W_lin[c * 128 + k];
    }
    if (i < 128) {
        int t = i >> 5, g = i & 31;
        float s = b_pre[i];
        for (int j = 0; j < 32; j++)
            s += b_edge[j] * W_pre[t * 3072 + (64 + j) * 32 + g];
        g_biasm[i] = s;
    }
    if (i == 0) {
        const double cnts[6] = {108477.0, 299931.0, 180702.0, 10767.0, 3.0, 2.0};
        double num = 0.0, den = 0.0;
        for (int d = 0; d < 6; d++) { num += cnts[d] * log((double)(d + 1) + 1.0); den += cnts[d]; }
        g_avglog = (float)(num / den);
    }
}

// ---------------- CSR build ----------------
__global__ void k_hist(const int* __restrict__ dst) {
    int i = blockIdx.x * 256 + threadIdx.x;
    if (i < EE) atomicAdd(&g_cnt[dst[i]], 1);
}

__global__ void k_scan1(void) {
    int b = blockIdx.x, t = threadIdx.x;
    int gi = b * 256 + t;
    int v = g_cnt[gi];
    int lane = t & 31, w = t >> 5;
    int incl = v;
#pragma unroll
    for (int off = 1; off < 32; off <<= 1) {
        int u = __shfl_up_sync(0xffffffffu, incl, off);
        if (lane >= off) incl += u;
    }
    __shared__ int wtot[8];
    __shared__ int woff[8];
    if (lane == 31) wtot[w] = incl;
    __syncthreads();
    if (t == 0) {
        int run = 0;
        for (int i = 0; i < 8; i++) { woff[i] = run; run += wtot[i]; }
        g_bsum[b] = run;
    }
    __syncthreads();
    g_rowptr[gi] = woff[w] + incl - v;
}

__global__ void k_scan2(void) {
    int t = threadIdx.x;
    int v = g_bsum[t];
    int lane = t & 31, w = t >> 5;
    int incl = v;
#pragma unroll
    for (int off = 1; off < 32; off <<= 1) {
        int u = __shfl_up_sync(0xffffffffu, incl, off);
        if (lane >= off) incl += u;
    }
    __shared__ int wtot[8];
    __shared__ int woff[8];
    if (lane == 31) wtot[w] = incl;
    __syncthreads();
    if (t == 0) {
        int run = 0;
        for (int i = 0; i < 8; i++) { woff[i] = run; run += wtot[i]; }
    }
    __syncthreads();
    g_bsum[t] = woff[w] + incl - v;
    if (t == 0) g_rowptr[NN] = EE;
}

__global__ void k_scan3(void) {
    int b = blockIdx.x, t = threadIdx.x;
    g_rowptr[b * 256 + t] += g_bsum[b];
}

__global__ void k_scatter(const int* __restrict__ dst) {
    int i = blockIdx.x * 256 + threadIdx.x;
    if (i < EE) {
        int d = dst[i];
        int slot = g_rowptr[d] + atomicAdd(&g_fill[d], 1);
        g_eid[slot] = i;
    }
}

// ---------------- node pre-parts (R9 __ldg version: L1-resident weights) ----------------
__global__ void k_ab(const float* __restrict__ x, const float* __restrict__ W_pre) {
    int i = blockIdx.x * 256 + threadIdx.x;
    if (i >= NN * 128) return;
    int n = i >> 7, ch = i & 127;
    int t = ch >> 5, g = ch & 31;
    const float* xr = x + (size_t)n * 128 + t * 32;
    const float* wa = W_pre + t * 3072 + g;
    const float* wb = wa + 1024;
    float a = 0.f, b = 0.f;
#pragma unroll
    for (int f = 0; f < 32; f++) {
        float xv = __ldg(&xr[f]);
        a = fmaf(xv, __ldg(&wa[f * 32]), a);
        b = fmaf(xv, __ldg(&wb[f * 32]), b);
    }
    g_a[i] = a; g_b[i] = b;
}

// ---------------- e-GEMM (tf32 mma, cp.async double-buffered) ----------------
// 128 rows/block, 8 warps x 16 rows. K=128 in 8 chunks of 16, raw floats staged
// async, tf32 convert at fragment read. Global kstep order 0..15 unchanged.
__global__ __launch_bounds__(256) void k_egemm(const float* __restrict__ ea) {
    __shared__ float sA[2][128 * 20];    // raw, stride 20 (bank-clean frag reads)
    __shared__ uint2 sB[16 * 4 * 32];    // all B frags [gks][nt][lane]
    int r0b = blockIdx.x * 128;
    int tid = threadIdx.x;
    int wid = tid >> 5, lane = tid & 31;
    int gid = lane >> 2, tig = lane & 3;
    int m0 = wid * 16;

    // stage all B fragments once (16KB)
    for (int i = tid; i < 2048; i += 256) {
        int l = i & 31, nt = (i >> 5) & 3, gks = i >> 7;
        int tg = l & 3, gd = l >> 2;
        int rk = gks * 8 + tg, cn = nt * 8 + gd;
        sB[i] = make_uint2(f2tf(g_WedgeT[rk * 32 + cn]),
                           f2tf(g_WedgeT[(rk + 4) * 32 + cn]));
    }

    // issue async copy of chunk kc into buffer buf (128 rows x 16 cols)
    #define EG_COPY(kc, buf) do {                                                   \
        for (int i = tid; i < 512; i += 256) {                                      \
            int r = i >> 2, kg = (i & 3) * 4;                                       \
            const float* src = &ea[(size_t)(r0b + r) * 128 + (kc) * 16 + kg];       \
            unsigned daddr = (unsigned)__cvta_generic_to_shared(&sA[buf][r * 20 + kg]); \
            asm volatile("cp.async.cg.shared.global [%0], [%1], 16;" :: "r"(daddr), "l"(src)); \
        }                                                                           \
        asm volatile("cp.async.commit_group;");                                     \
    } while (0)

    float acc[4][4];
#pragma unroll
    for (int nt = 0; nt < 4; nt++)
#pragma unroll
        for (int q = 0; q < 4; q++) acc[nt][q] = 0.f;

    EG_COPY(0, 0);
    for (int kc = 0; kc < 8; kc++) {
        int buf = kc & 1;
        if (kc < 7) {
            EG_COPY(kc + 1, buf ^ 1);
            asm volatile("cp.async.wait_group 1;");
        } else {
            asm volatile("cp.async.wait_group 0;");
        }
        __syncthreads();
#pragma unroll
        for (int ks = 0; ks < 2; ks++) {
            const float* Ab = &sA[buf][0];
            unsigned a0 = f2tf(Ab[(m0 + gid) * 20 + ks * 8 + tig]);
            unsigned a1 = f2tf(Ab[(m0 + gid + 8) * 20 + ks * 8 + tig]);
            unsigned a2 = f2tf(Ab[(m0 + gid) * 20 + ks * 8 + tig + 4]);
            unsigned a3 = f2tf(Ab[(m0 + gid + 8) * 20 + ks * 8 + tig + 4]);
            int gks = kc * 2 + ks;
#pragma unroll
            for (int nt = 0; nt < 4; nt++) {
                uint2 b = sB[(gks * 4 + nt) * 32 + lane];
                mma_tf32(acc[nt][0], acc[nt][1], acc[nt][2], acc[nt][3],
                         a0, a1, a2, a3, b.x, b.y);
            }
        }
        __syncthreads();
    }
    #undef EG_COPY

    int base = r0b + m0;
#pragma unroll
    for (int nt = 0; nt < 4; nt++) {
        int col = nt * 8 + tig * 2;
        *(float2*)&g_e[(size_t)(base + gid) * 32 + col] = make_float2(acc[nt][0], acc[nt][1]);
        *(float2*)&g_e[(size_t)(base + gid + 8) * 32 + col] = make_float2(acc[nt][2], acc[nt][3]);
    }
}

// ---------------- c-GEMM (tf32 mma): c[E,128] = e[E,32] @ Wpre_e ----------------
__global__ __launch_bounds__(256) void k_cgemm(const float* __restrict__ W_pre) {
    __shared__ unsigned sE[128 * 36];
    __shared__ uint2    sB[4 * 16 * 32];
    int r0b = blockIdx.x * 128;
    int tid = threadIdx.x;
    int wid = tid >> 5, lane = tid & 31;
    int gid = lane >> 2, tig = lane & 3;
    int m0 = wid * 16;

    for (int i = tid; i < 128 * 8; i += 256) {
        int r = i >> 3, kg = (i & 7) * 4;
        float4 v = *(const float4*)&g_e[(size_t)(r0b + r) * 32 + kg];
        *(uint4*)&sE[r * 36 + kg] = make_uint4(f2tf(v.x), f2tf(v.y), f2tf(v.z), f2tf(v.w));
    }
    for (int i = tid; i < 2048; i += 256) {
        int l = i & 31, nt = (i >> 5) & 15, ks = i >> 9;
        int tg = l & 3, gd = l >> 2;
        int j = ks * 8 + tg;
        int o = nt * 8 + gd;
        int t = o >> 5, g = o & 31;
        sB[i] = make_uint2(f2tf(W_pre[t * 3072 + (64 + j) * 32 + g]),
                           f2tf(W_pre[t * 3072 + (64 + j + 4) * 32 + g]));
    }
    __syncthreads();

    float acc[16][4];
#pragma unroll
    for (int nt = 0; nt < 16; nt++)
#pragma unroll
        for (int q = 0; q < 4; q++) acc[nt][q] = 0.f;

#pragma unroll
    for (int ks = 0; ks < 4; ks++) {
        unsigned a0 = sE[(m0 + gid) * 36 + ks * 8 + tig];
        unsigned a1 = sE[(m0 + gid + 8) * 36 + ks * 8 + tig];
        unsigned a2 = sE[(m0 + gid) * 36 + ks * 8 + tig + 4];
        unsigned a3 = sE[(m0 + gid + 8) * 36 + ks * 8 + tig + 4];
#pragma unroll
        for (int nt = 0; nt < 16; nt++) {
            uint2 b = sB[(ks * 16 + nt) * 32 + lane];
            mma_tf32(acc[nt][0], acc[nt][1], acc[nt][2], acc[nt][3],
                     a0, a1, a2, a3, b.x, b.y);
        }
    }
    int base = r0b + m0;
#pragma unroll
    for (int nt = 0; nt < 16; nt++) {
        int col = nt * 8 + tig * 2;
        *(float2*)&g_c[(size_t)(base + gid) * 128 + col] = make_float2(acc[nt][0], acc[nt][1]);
        *(float2*)&g_c[(size_t)(base + gid + 8) * 128 + col] = make_float2(acc[nt][2], acc[nt][3]);
    }
}

// ---------------- aggregation: one warp per node (sorted edge list, 2-edge ILP) ----------------
__global__ __launch_bounds__(256) void k_agg(const int* __restrict__ srcp) {
    __shared__ int s_eid[8][128];
    int w = threadIdx.x >> 5;
    int lane = threadIdx.x & 31;
    int n = blockIdx.x * 8 + w;
    if (n >= NN) return;
    int start = g_rowptr[n], end = g_rowptr[n + 1];
    int deg = end - start;
    int msort = deg < 128 ? deg : 128;

    for (int j = lane; j < msort; j += 32) s_eid[w][j] = g_eid[start + j];
    __syncwarp();
    for (int pass = 0; pass < msort; pass++) {
        int off = pass & 1;
        for (int j = lane; 2 * j + 1 + off < msort; j += 32) {
            int i0 = 2 * j + off, i1 = i0 + 1;
            int a = s_eid[w][i0], b = s_eid[w][i1];
            if (a > b) { s_eid[w][i0] = b; s_eid[w][i1] = a; }
        }
        __syncwarp();
    }

    float4 base = *(const float4*)&g_a[(size_t)n * 128 + lane * 4];
    float4 bm   = *(const float4*)&g_biasm[lane * 4];
    base.x += bm.x; base.y += bm.y; base.z += bm.z; base.w += bm.w;

    float4 s  = make_float4(0.f, 0.f, 0.f, 0.f);
    float4 sq = make_float4(0.f, 0.f, 0.f, 0.f);
    float4 mx = make_float4(-FMAXV, -FMAXV, -FMAXV, -FMAXV);
    float4 mn = make_float4( FMAXV,  FMAXV,  FMAXV,  FMAXV);

    int sl = 0;
    for (; sl + 2 <= deg; sl += 2) {
        int eid0 = (sl     < 128) ? s_eid[w][sl]     : __ldg(&g_eid[start + sl]);
        int eid1 = (sl + 1 < 128) ? s_eid[w][sl + 1] : __ldg(&g_eid[start + sl + 1]);
        int sn0 = __ldg(&srcp[eid0]);
        int sn1 = __ldg(&srcp[eid1]);
        float4 c0 = *(const float4*)&g_c[(size_t)eid0 * 128 + lane * 4];
        float4 b0 = *(const float4*)&g_b[(size_t)sn0 * 128 + lane * 4];
        float4 c1 = *(const float4*)&g_c[(size_t)eid1 * 128 + lane * 4];
        float4 b1 = *(const float4*)&g_b[(size_t)sn1 * 128 + lane * 4];

        float m0 = base.x + b0.x + c0.x;
        float m1 = base.y + b0.y + c0.y;
        float m2 = base.z + b0.z + c0.z;
        float m3 = base.w + b0.w + c0.w;
        s.x += m0; s.y += m1; s.z += m2; s.w += m3;
        sq.x = fmaf(m0, m0, sq.x); sq.y = fmaf(m1, m1, sq.y);
        sq.z = fmaf(m2, m2, sq.z); sq.w = fmaf(m3, m3, sq.w);
        mx.x = fmaxf(mx.x, m0); mx.y = fmaxf(mx.y, m1); mx.z = fmaxf(mx.z, m2); mx.w = fmaxf(mx.w, m3);
        mn.x = fminf(mn.x, m0); mn.y = fminf(mn.y, m1); mn.z = fminf(mn.z, m2); mn.w = fminf(mn.w, m3);

        float p0 = base.x + b1.x + c1.x;
        float p1 = base.y + b1.y + c1.y;
        float p2 = base.z + b1.z + c1.z;
        float p3 = base.w + b1.w + c1.w;
        s.x += p0; s.y += p1; s.z += p2; s.w += p3;
        sq.x = fmaf(p0, p0, sq.x); sq.y = fmaf(p1, p1, sq.y);
        sq.z = fmaf(p2, p2, sq.z); sq.w = fmaf(p3, p3, sq.w);
        mx.x = fmaxf(mx.x, p0); mx.y = fmaxf(mx.y, p1); mx.z = fmaxf(mx.z, p2); mx.w = fmaxf(mx.w, p3);
        mn.x = fminf(mn.x, p0); mn.y = fminf(mn.y, p1); mn.z = fminf(mn.z, p2); mn.w = fminf(mn.w, p3);
    }
    for (; sl < deg; sl++) {
        int eid = (sl < 128) ? s_eid[w][sl] : __ldg(&g_eid[start + sl]);
        int sn  = __ldg(&srcp[eid]);
        float4 c = *(const float4*)&g_c[(size_t)eid * 128 + lane * 4];
        float4 b = *(const float4*)&g_b[(size_t)sn * 128 + lane * 4];
        float m0 = base.x + b.x + c.x;
        float m1 = base.y + b.y + c.y;
        float m2 = base.z + b.z + c.z;
        float m3 = base.w + b.w + c.w;
        s.x += m0; s.y += m1; s.z += m2; s.w += m3;
        sq.x = fmaf(m0, m0, sq.x); sq.y = fmaf(m1, m1, sq.y);
        sq.z = fmaf(m2, m2, sq.z); sq.w = fmaf(m3, m3, sq.w);
        mx.x = fmaxf(mx.x, m0); mx.y = fmaxf(mx.y, m1); mx.z = fmaxf(mx.z, m2); mx.w = fmaxf(mx.w, m3);
        mn.x = fminf(mn.x, m0); mn.y = fminf(mn.y, m1); mn.z = fminf(mn.z, m2); mn.w = fminf(mn.w, m3);
    }
    if (deg == 0) {
        mx = make_float4(0.f, 0.f, 0.f, 0.f);
        mn = make_float4(0.f, 0.f, 0.f, 0.f);
    }
    float cs = (float)(deg > 0 ? deg : 1);
    float inv = 1.0f / cs;
    float4 mean = make_float4(s.x * inv, s.y * inv, s.z * inv, s.w * inv);
    float4 msq  = make_float4(sq.x * inv, sq.y * inv, sq.z * inv, sq.w * inv);
    float4 sd;
    sd.x = sqrtf(fmaxf(msq.x - mean.x * mean.x, 0.f) + 1e-5f);
    sd.y = sqrtf(fmaxf(msq.y - mean.y * mean.y, 0.f) + 1e-5f);
    sd.z = sqrtf(fmaxf(msq.z - mean.z * mean.z, 0.f) + 1e-5f);
    sd.w = sqrtf(fmaxf(msq.w - mean.w * mean.w, 0.f) + 1e-5f);

    int t = (lane * 4) >> 5, g0 = (lane * 4) & 31;
    float* aggp = &g_agg[(size_t)n * 512 + t * 128 + g0];
    *(float4*)&aggp[0]  = mean;
    *(float4*)&aggp[32] = mx;
    *(float4*)&aggp[64] = mn;
    *(float4*)&aggp[96] = sd;

    if (lane == 0) {
        float avg = g_avglog;
        float logd = logf((float)deg + 1.0f);
        g_s1[n] = logd / avg;
        g_s2[n] = (deg == 0) ? 1.0f : (avg / logd);
    }
}

// ---------------- post-MLP (tf32 mma) ----------------
__global__ __launch_bounds__(256) void k_post(const float* __restrict__ x,
                                              const float* __restrict__ W_post,
                                              const float* __restrict__ b_post) {
    __shared__ unsigned sA[64 * 36];
    __shared__ uint2    sB0[4 * 4 * 32];
    __shared__ uint2    sB1[4 * 4 * 32];
    __shared__ uint2    sB2[4 * 4 * 32];
    __shared__ uint2    sB3[4 * 4 * 32];
    __shared__ float    s_c1[64], s_c2[64];

    int t  = blockIdx.y;
    int n0 = blockIdx.x * 64;
    int tid = threadIdx.x;
    int wid = tid >> 5, lane = tid & 31;
    int gid = lane >> 2, tig = lane & 3;
    int mt = wid >> 1, nh = wid & 1;
    int m0 = mt * 16;
    const float* Wt = W_post + (size_t)t * 416 * 32;

    for (int i = tid; i < 64 * 8; i += 256) {
        int r = i >> 3, fg = (i & 7) * 4;
        float4 v = *(const float4*)&x[(size_t)(n0 + r) * 128 + t * 32 + fg];
        *(uint4*)&sA[r * 36 + fg] = make_uint4(f2tf(v.x), f2tf(v.y), f2tf(v.z), f2tf(v.w));
    }
    for (int i = tid; i < 512; i += 256) {
        int l = i & 31, nt = (i >> 5) & 3, ks = i >> 7;
        int tg = l & 3, gd = l >> 2;
        int rk = ks * 8 + tg, cn = nt * 8 + gd;
        sB0[i] = make_uint2(f2tf(Wt[rk * 32 + cn]), f2tf(Wt[(rk + 4) * 32 + cn]));
    }
    if (tid < 64) { s_c1[tid] = g_s1[n0 + tid]; s_c2[tid] = g_s2[n0 + tid]; }
    __syncthreads();

    float acc1[2][4], acc2[2][4], acc3[2][4];
#pragma unroll
    for (int nl = 0; nl < 2; nl++)
#pragma unroll
        for (int q = 0; q < 4; q++) { acc1[nl][q] = 0.f; acc2[nl][q] = 0.f; acc3[nl][q] = 0.f; }

#pragma unroll
    for (int ks = 0; ks < 4; ks++) {
        unsigned a0 = sA[(m0 + gid) * 36 + ks * 8 + tig];
        unsigned a1 = sA[(m0 + gid + 8) * 36 + ks * 8 + tig];
        unsigned a2 = sA[(m0 + gid) * 36 + ks * 8 + tig + 4];
        unsigned a3 = sA[(m0 + gid + 8) * 36 + ks * 8 + tig + 4];
#pragma unroll
        for (int nl = 0; nl < 2; nl++) {
            int nt = nh * 2 + nl;
            uint2 b = sB0[(ks * 4 + nt) * 32 + lane];
            mma_tf32(acc1[nl][0], acc1[nl][1], acc1[nl][2], acc1[nl][3],
                     a0, a1, a2, a3, b.x, b.y);
        }
    }

    for (int kt = 0; kt < 4; kt++) {
        int k0 = kt * 32;
        __syncthreads();
        for (int i = tid; i < 64 * 8; i += 256) {
            int r = i >> 3, kg = (i & 7) * 4;
            float4 v = *(const float4*)&g_agg[(size_t)(n0 + r) * 512 + t * 128 + k0 + kg];
            *(uint4*)&sA[r * 36 + kg] = make_uint4(f2tf(v.x), f2tf(v.y), f2tf(v.z), f2tf(v.w));
        }
        for (int i = tid; i < 512; i += 256) {
            int l = i & 31, nt = (i >> 5) & 3, ks = i >> 7;
            int tg = l & 3, gd = l >> 2;
            int rk = k0 + ks * 8 + tg, cn = nt * 8 + gd;
            sB1[i] = make_uint2(f2tf(Wt[(32 + rk) * 32 + cn]),  f2tf(Wt[(32 + rk + 4) * 32 + cn]));
            sB2[i] = make_uint2(f2tf(Wt[(160 + rk) * 32 + cn]), f2tf(Wt[(160 + rk + 4) * 32 + cn]));
            sB3[i] = make_uint2(f2tf(Wt[(288 + rk) * 32 + cn]), f2tf(Wt[(288 + rk + 4) * 32 + cn]));
        }
        __syncthreads();
#pragma unroll
        for (int ks = 0; ks < 4; ks++) {
            unsigned a0 = sA[(m0 + gid) * 36 + ks * 8 + tig];
            unsigned a1 = sA[(m0 + gid + 8) * 36 + ks * 8 + tig];
            unsigned a2 = sA[(m0 + gid) * 36 + ks * 8 + tig + 4];
            unsigned a3 = sA[(m0 + gid + 8) * 36 + ks * 8 + tig + 4];
#pragma unroll
            for (int nl = 0; nl < 2; nl++) {
                int nt = nh * 2 + nl;
                uint2 b1 = sB1[(ks * 4 + nt) * 32 + lane];
                uint2 b2 = sB2[(ks * 4 + nt) * 32 + lane];
                uint2 b3 = sB3[(ks * 4 + nt) * 32 + lane];
                mma_tf32(acc1[nl][0], acc1[nl][1], acc1[nl][2], acc1[nl][3],
                         a0, a1, a2, a3, b1.x, b1.y);
                mma_tf32(acc2[nl][0], acc2[nl][1], acc2[nl][2], acc2[nl][3],
                         a0, a1, a2, a3, b2.x, b2.y);
                mma_tf32(acc3[nl][0], acc3[nl][1], acc3[nl][2], acc3[nl][3],
                         a0, a1, a2, a3, b3.x, b3.y);
            }
        }
    }

#pragma unroll
    for (int nl = 0; nl < 2; nl++) {
        int nt = nh * 2 + nl;
        int col = nt * 8 + tig * 2;
        float bp0 = b_post[t * 32 + col];
        float bp1 = b_post[t * 32 + col + 1];
        int r0 = m0 + gid;
        float c1a = s_c1[r0], c2a = s_c2[r0];
        float y00 = acc1[nl][0] + c1a * acc2[nl][0] + c2a * acc3[nl][0] + bp0;
        float y01 = acc1[nl][1] + c1a * acc2[nl][1] + c2a * acc3[nl][1] + bp1;
        *(float2*)&g_Z[(size_t)(n0 + r0) * 128 + t * 32 + col] = make_float2(y00, y01);
        int r1 = m0 + gid + 8;
        float c1b = s_c1[r1], c2b = s_c2[r1];
        float y10 = acc1[nl][2] + c1b * acc2[nl][2] + c2b * acc3[nl][2] + bp0;
        float y11 = acc1[nl][3] + c1b * acc2[nl][3] + c2b * acc3[nl][3] + bp1;
        *(float2*)&g_Z[(size_t)(n0 + r1) * 128 + t * 32 + col] = make_float2(y10, y11);
    }
}

// ---------------- final (tf32 mma): out = Z @ W_lin^T + b_lin + x ----------------
__global__ __launch_bounds__(256) void k_final(const float* __restrict__ x,
                                               const float* __restrict__ b_lin,
                                               float* __restrict__ out) {
    __shared__ unsigned sA[128 * 36];
    __shared__ uint2    sB[4 * 16 * 32];
    int r0b = blockIdx.x * 128;
    int tid = threadIdx.x;
    int wid = tid >> 5, lane = tid & 31;
    int gid = lane >> 2, tig = lane & 3;
    int m0 = wid * 16;

    float acc[16][4];
#pragma unroll
    for (int nt = 0; nt < 16; nt++)
#pragma unroll
        for (int q = 0; q < 4; q++) acc[nt][q] = 0.f;

    for (int k0 = 0; k0 < 128; k0 += 32) {
        __syncthreads();
        for (int i = tid; i < 128 * 8; i += 256) {
            int r = i >> 3, kg = (i & 7) * 4;
            float4 v = *(const float4*)&g_Z[(size_t)(r0b + r) * 128 + k0 + kg];
            *(uint4*)&sA[r * 36 + kg] = make_uint4(f2tf(v.x), f2tf(v.y), f2tf(v.z), f2tf(v.w));
        }
        for (int i = tid; i < 2048; i += 256) {
            int l = i & 31, nt = (i >> 5) & 15, ks = i >> 9;
            int tg = l & 3, gd = l >> 2;
            int rk = k0 + ks * 8 + tg, cn = nt * 8 + gd;
            sB[i] = make_uint2(f2tf(g_WlinT[rk * 128 + cn]),
                               f2tf(g_WlinT[(rk + 4) * 128 + cn]));
        }
        __syncthreads();
#pragma unroll
        for (int ks = 0; ks < 4; ks++) {
            unsigned a0 = sA[(m0 + gid) * 36 + ks * 8 + tig];
            unsigned a1 = sA[(m0 + gid + 8) * 36 + ks * 8 + tig];
            unsigned a2 = sA[(m0 + gid) * 36 + ks * 8 + tig + 4];
            unsigned a3 = sA[(m0 + gid + 8) * 36 + ks * 8 + tig + 4];
#pragma unroll
            for (int nt = 0; nt < 16; nt++) {
                uint2 b = sB[(ks * 16 + nt) * 32 + lane];
                mma_tf32(acc[nt][0], acc[nt][1], acc[nt][2], acc[nt][3],
                         a0, a1, a2, a3, b.x, b.y);
            }
        }
    }
    int base = r0b + m0;
#pragma unroll
    for (int nt = 0; nt < 16; nt++) {
        int col = nt * 8 + tig * 2;
        float2 bl = *(const float2*)&b_lin[col];
        float2 x0 = *(const float2*)&x[(size_t)(base + gid) * 128 + col];
        float2 x1 = *(const float2*)&x[(size_t)(base + gid + 8) * 128 + col];
        *(float2*)&out[(size_t)(base + gid) * 128 + col] =
            make_float2(acc[nt][0] + bl.x + x0.x, acc[nt][1] + bl.y + x0.y);
        *(float2*)&out[(size_t)(base + gid + 8) * 128 + col] =
            make_float2(acc[nt][2] + bl.x + x1.x, acc[nt][3] + bl.y + x1.y);
    }
}

// ---------------- launch (egemm in profiled slot #4) ----------------
extern "C" void kernel_launch(void* const* d_in, const int* in_sizes, int n_in,
                              void* d_out, int out_size) {
    const float* x         = (const float*)d_in[0];
    const float* edge_attr = (const float*)d_in[1];
    const int*   edge_idx  = (const int*)d_in[2];
    const float* W_edge    = (const float*)d_in[3];
    const float* b_edge    = (const float*)d_in[4];
    const float* W_pre     = (const float*)d_in[5];
    const float* b_pre     = (const float*)d_in[6];
    const float* W_post    = (const float*)d_in[7];
    const float* b_post    = (const float*)d_in[8];
    const float* W_lin     = (const float*)d_in[9];
    const float* b_lin     = (const float*)d_in[10];
    float* out = (float*)d_out;

    const int* srcp = edge_idx;
    const int* dstp = edge_idx + EE;

    k_zero<<<NN / 256, 256>>>();
    k_prep<<<64, 256>>>(W_edge, W_lin, W_pre, b_pre, b_edge);
    k_hist<<<EE / 256, 256>>>(dstp);
    k_egemm<<<EE / 128, 256>>>(edge_attr);       // profiled slot
    k_scan1<<<256, 256>>>();
    k_scan2<<<1, 256>>>();
    k_scan3<<<256, 256>>>();
    k_scatter<<<EE / 256, 256>>>(dstp);
    k_ab<<<(NN * 128) / 256, 256>>>(x, W_pre);
    k_cgemm<<<EE / 128, 256>>>(W_pre);
    k_agg<<<NN / 8, 256>>>(srcp);
    k_post<<<dim3(NN / 64, 4), 256>>>(x, W_post, b_post);
    k_final<<<NN / 128, 256>>>(x, b_lin, out);
}

// round 15
// speedup vs baseline: 1.1180x; 1.0072x over previous
#include <cuda_runtime.h>
#include <cuda_bf16.h>
#include <math.h>
#include <stdint.h>
#include <stddef.h>

#define NN 65536
#define EE 1048576
#define FMAXV 3.402823466e38f

// ---------------- static device scratch (no allocations) ----------------
__device__ float g_e[(size_t)EE * 32];      // edge_attr @ W_edge^T
__device__ float g_c[(size_t)EE * 128];     // e @ Wpre_edgepart
__device__ float g_a[(size_t)NN * 128];     // dst-side node pre-part
__device__ float g_b[(size_t)NN * 128];     // src-side node pre-part
__device__ float g_agg[(size_t)NN * 512];   // per node/tower: [mean|mx|mn|std] x32
__device__ float g_Z[(size_t)NN * 128];     // post-MLP output
__device__ float g_s1[NN];
__device__ float g_s2[NN];
__device__ int   g_cnt[NN];
__device__ int   g_fill[NN];
__device__ int   g_rowptr[NN + 1];
__device__ int   g_eid[EE];
__device__ int   g_bsum[256];
__device__ float g_biasm[128];
__device__ float g_WedgeT[128 * 32];        // [k][f]
__device__ float g_WlinT[128 * 128];        // [k][c]
__device__ float g_avglog;

// ---------------- tf32 mma helpers ----------------
__device__ __forceinline__ unsigned f2tf(float x) {
    unsigned r;
    asm("cvt.rna.tf32.f32 %0, %1;" : "=r"(r) : "f"(x));
    return r;
}
__device__ __forceinline__ void mma_tf32(float& d0, float& d1, float& d2, float& d3,
                                         unsigned a0, unsigned a1, unsigned a2, unsigned a3,
                                         unsigned b0, unsigned b1) {
    asm("mma.sync.aligned.m16n8k8.row.col.f32.tf32.tf32.f32 "
        "{%0,%1,%2,%3},{%4,%5,%6,%7},{%8,%9},{%0,%1,%2,%3};"
        : "+f"(d0), "+f"(d1), "+f"(d2), "+f"(d3)
        : "r"(a0), "r"(a1), "r"(a2), "r"(a3), "r"(b0), "r"(b1));
}

// ---------------- setup ----------------
__global__ void k_zero(void) {
    int i = blockIdx.x * 256 + threadIdx.x;
    if (i < NN) { g_cnt[i] = 0; g_fill[i] = 0; }
}

__global__ void k_prep(const float* __restrict__ W_edge, const float* __restrict__ W_lin,
                       const float* __restrict__ W_pre, const float* __restrict__ b_pre,
                       const float* __restrict__ b_edge) {
    int i = blockIdx.x * 256 + threadIdx.x;
    if (i < 128 * 32) {
        int k = i >> 5, f = i & 31;
        g_WedgeT[i] = W_edge[f * 128 + k];
    }
    if (i < 128 * 128) {
        int k = i >> 7, c = i & 127;
        g_WlinT[i] = W_lin[c * 128 + k];
    }
    if (i < 128) {
        int t = i >> 5, g = i & 31;
        float s = b_pre[i];
        for (int j = 0; j < 32; j++)
            s += b_edge[j] * W_pre[t * 3072 + (64 + j) * 32 + g];
        g_biasm[i] = s;
    }
    if (i == 0) {
        const double cnts[6] = {108477.0, 299931.0, 180702.0, 10767.0, 3.0, 2.0};
        double num = 0.0, den = 0.0;
        for (int d = 0; d < 6; d++) { num += cnts[d] * log((double)(d + 1) + 1.0); den += cnts[d]; }
        g_avglog = (float)(num / den);
    }
}

// ---------------- CSR build ----------------
__global__ void k_hist(const int* __restrict__ dst) {
    int i = blockIdx.x * 256 + threadIdx.x;
    if (i < EE) atomicAdd(&g_cnt[dst[i]], 1);
}

__global__ void k_scan1(void) {
    int b = blockIdx.x, t = threadIdx.x;
    int gi = b * 256 + t;
    int v = g_cnt[gi];
    int lane = t & 31, w = t >> 5;
    int incl = v;
#pragma unroll
    for (int off = 1; off < 32; off <<= 1) {
        int u = __shfl_up_sync(0xffffffffu, incl, off);
        if (lane >= off) incl += u;
    }
    __shared__ int wtot[8];
    __shared__ int woff[8];
    if (lane == 31) wtot[w] = incl;
    __syncthreads();
    if (t == 0) {
        int run = 0;
        for (int i = 0; i < 8; i++) { woff[i] = run; run += wtot[i]; }
        g_bsum[b] = run;
    }
    __syncthreads();
    g_rowptr[gi] = woff[w] + incl - v;
}

__global__ void k_scan2(void) {
    int t = threadIdx.x;
    int v = g_bsum[t];
    int lane = t & 31, w = t >> 5;
    int incl = v;
#pragma unroll
    for (int off = 1; off < 32; off <<= 1) {
        int u = __shfl_up_sync(0xffffffffu, incl, off);
        if (lane >= off) incl += u;
    }
    __shared__ int wtot[8];
    __shared__ int woff[8];
    if (lane == 31) wtot[w] = incl;
    __syncthreads();
    if (t == 0) {
        int run = 0;
        for (int i = 0; i < 8; i++) { woff[i] = run; run += wtot[i]; }
    }
    __syncthreads();
    g_bsum[t] = woff[w] + incl - v;
    if (t == 0) g_rowptr[NN] = EE;
}

__global__ void k_scan3(void) {
    int b = blockIdx.x, t = threadIdx.x;
    g_rowptr[b * 256 + t] += g_bsum[b];
}

__global__ void k_scatter(const int* __restrict__ dst) {
    int i = blockIdx.x * 256 + threadIdx.x;
    if (i < EE) {
        int d = dst[i];
        int slot = g_rowptr[d] + atomicAdd(&g_fill[d], 1);
        g_eid[slot] = i;
    }
}

// ---------------- node pre-parts (__ldg: L1-resident weights) ----------------
__global__ void k_ab(const float* __restrict__ x, const float* __restrict__ W_pre) {
    int i = blockIdx.x * 256 + threadIdx.x;
    if (i >= NN * 128) return;
    int n = i >> 7, ch = i & 127;
    int t = ch >> 5, g = ch & 31;
    const float* xr = x + (size_t)n * 128 + t * 32;
    const float* wa = W_pre + t * 3072 + g;
    const float* wb = wa + 1024;
    float a = 0.f, b = 0.f;
#pragma unroll
    for (int f = 0; f < 32; f++) {
        float xv = __ldg(&xr[f]);
        a = fmaf(xv, __ldg(&wa[f * 32]), a);
        b = fmaf(xv, __ldg(&wb[f * 32]), b);
    }
    g_a[i] = a; g_b[i] = b;
}

// ---------------- e-GEMM (tf32 mma, cp.async double-buffered) ----------------
__global__ __launch_bounds__(256) void k_egemm(const float* __restrict__ ea) {
    __shared__ float sA[2][128 * 20];
    __shared__ uint2 sB[16 * 4 * 32];
    int r0b = blockIdx.x * 128;
    int tid = threadIdx.x;
    int wid = tid >> 5, lane = tid & 31;
    int gid = lane >> 2, tig = lane & 3;
    int m0 = wid * 16;

    for (int i = tid; i < 2048; i += 256) {
        int l = i & 31, nt = (i >> 5) & 3, gks = i >> 7;
        int tg = l & 3, gd = l >> 2;
        int rk = gks * 8 + tg, cn = nt * 8 + gd;
        sB[i] = make_uint2(f2tf(g_WedgeT[rk * 32 + cn]),
                           f2tf(g_WedgeT[(rk + 4) * 32 + cn]));
    }

    #define EG_COPY(kc, buf) do {                                                   \
        for (int i = tid; i < 512; i += 256) {                                      \
            int r = i >> 2, kg = (i & 3) * 4;                                       \
            const float* src = &ea[(size_t)(r0b + r) * 128 + (kc) * 16 + kg];       \
            unsigned daddr = (unsigned)__cvta_generic_to_shared(&sA[buf][r * 20 + kg]); \
            asm volatile("cp.async.cg.shared.global [%0], [%1], 16;" :: "r"(daddr), "l"(src)); \
        }                                                                           \
        asm volatile("cp.async.commit_group;");                                     \
    } while (0)

    float acc[4][4];
#pragma unroll
    for (int nt = 0; nt < 4; nt++)
#pragma unroll
        for (int q = 0; q < 4; q++) acc[nt][q] = 0.f;

    EG_COPY(0, 0);
    for (int kc = 0; kc < 8; kc++) {
        int buf = kc & 1;
        if (kc < 7) {
            EG_COPY(kc + 1, buf ^ 1);
            asm volatile("cp.async.wait_group 1;");
        } else {
            asm volatile("cp.async.wait_group 0;");
        }
        __syncthreads();
#pragma unroll
        for (int ks = 0; ks < 2; ks++) {
            const float* Ab = &sA[buf][0];
            unsigned a0 = f2tf(Ab[(m0 + gid) * 20 + ks * 8 + tig]);
            unsigned a1 = f2tf(Ab[(m0 + gid + 8) * 20 + ks * 8 + tig]);
            unsigned a2 = f2tf(Ab[(m0 + gid) * 20 + ks * 8 + tig + 4]);
            unsigned a3 = f2tf(Ab[(m0 + gid + 8) * 20 + ks * 8 + tig + 4]);
            int gks = kc * 2 + ks;
#pragma unroll
            for (int nt = 0; nt < 4; nt++) {
                uint2 b = sB[(gks * 4 + nt) * 32 + lane];
                mma_tf32(acc[nt][0], acc[nt][1], acc[nt][2], acc[nt][3],
                         a0, a1, a2, a3, b.x, b.y);
            }
        }
        __syncthreads();
    }
    #undef EG_COPY

    int base = r0b + m0;
#pragma unroll
    for (int nt = 0; nt < 4; nt++) {
        int col = nt * 8 + tig * 2;
        *(float2*)&g_e[(size_t)(base + gid) * 32 + col] = make_float2(acc[nt][0], acc[nt][1]);
        *(float2*)&g_e[(size_t)(base + gid + 8) * 32 + col] = make_float2(acc[nt][2], acc[nt][3]);
    }
}

// ---------------- c-GEMM (tf32 mma): c[E,128] = e[E,32] @ Wpre_e ----------------
__global__ __launch_bounds__(256) void k_cgemm(const float* __restrict__ W_pre) {
    __shared__ unsigned sE[128 * 36];
    __shared__ uint2    sB[4 * 16 * 32];
    int r0b = blockIdx.x * 128;
    int tid = threadIdx.x;
    int wid = tid >> 5, lane = tid & 31;
    int gid = lane >> 2, tig = lane & 3;
    int m0 = wid * 16;

    for (int i = tid; i < 128 * 8; i += 256) {
        int r = i >> 3, kg = (i & 7) * 4;
        float4 v = *(const float4*)&g_e[(size_t)(r0b + r) * 32 + kg];
        *(uint4*)&sE[r * 36 + kg] = make_uint4(f2tf(v.x), f2tf(v.y), f2tf(v.z), f2tf(v.w));
    }
    for (int i = tid; i < 2048; i += 256) {
        int l = i & 31, nt = (i >> 5) & 15, ks = i >> 9;
        int tg = l & 3, gd = l >> 2;
        int j = ks * 8 + tg;
        int o = nt * 8 + gd;
        int t = o >> 5, g = o & 31;
        sB[i] = make_uint2(f2tf(W_pre[t * 3072 + (64 + j) * 32 + g]),
                           f2tf(W_pre[t * 3072 + (64 + j + 4) * 32 + g]));
    }
    __syncthreads();

    float acc[16][4];
#pragma unroll
    for (int nt = 0; nt < 16; nt++)
#pragma unroll
        for (int q = 0; q < 4; q++) acc[nt][q] = 0.f;

#pragma unroll
    for (int ks = 0; ks < 4; ks++) {
        unsigned a0 = sE[(m0 + gid) * 36 + ks * 8 + tig];
        unsigned a1 = sE[(m0 + gid + 8) * 36 + ks * 8 + tig];
        unsigned a2 = sE[(m0 + gid) * 36 + ks * 8 + tig + 4];
        unsigned a3 = sE[(m0 + gid + 8) * 36 + ks * 8 + tig + 4];
#pragma unroll
        for (int nt = 0; nt < 16; nt++) {
            uint2 b = sB[(ks * 16 + nt) * 32 + lane];
            mma_tf32(acc[nt][0], acc[nt][1], acc[nt][2], acc[nt][3],
                     a0, a1, a2, a3, b.x, b.y);
        }
    }
    int base = r0b + m0;
#pragma unroll
    for (int nt = 0; nt < 16; nt++) {
        int col = nt * 8 + tig * 2;
        *(float2*)&g_c[(size_t)(base + gid) * 128 + col] = make_float2(acc[nt][0], acc[nt][1]);
        *(float2*)&g_c[(size_t)(base + gid + 8) * 128 + col] = make_float2(acc[nt][2], acc[nt][3]);
    }
}

// ---------------- aggregation: one warp per node (sorted edge list, 2-edge ILP) ----------------
__global__ __launch_bounds__(256) void k_agg(const int* __restrict__ srcp) {
    __shared__ int s_eid[8][128];
    int w = threadIdx.x >> 5;
    int lane = threadIdx.x & 31;
    int n = blockIdx.x * 8 + w;
    if (n >= NN) return;
    int start = g_rowptr[n], end = g_rowptr[n + 1];
    int deg = end - start;
    int msort = deg < 128 ? deg : 128;

    for (int j = lane; j < msort; j += 32) s_eid[w][j] = g_eid[start + j];
    __syncwarp();
    for (int pass = 0; pass < msort; pass++) {
        int off = pass & 1;
        for (int j = lane; 2 * j + 1 + off < msort; j += 32) {
            int i0 = 2 * j + off, i1 = i0 + 1;
            int a = s_eid[w][i0], b = s_eid[w][i1];
            if (a > b) { s_eid[w][i0] = b; s_eid[w][i1] = a; }
        }
        __syncwarp();
    }

    float4 base = *(const float4*)&g_a[(size_t)n * 128 + lane * 4];
    float4 bm   = *(const float4*)&g_biasm[lane * 4];
    base.x += bm.x; base.y += bm.y; base.z += bm.z; base.w += bm.w;

    float4 s  = make_float4(0.f, 0.f, 0.f, 0.f);
    float4 sq = make_float4(0.f, 0.f, 0.f, 0.f);
    float4 mx = make_float4(-FMAXV, -FMAXV, -FMAXV, -FMAXV);
    float4 mn = make_float4( FMAXV,  FMAXV,  FMAXV,  FMAXV);

    int sl = 0;
    for (; sl + 2 <= deg; sl += 2) {
        int eid0 = (sl     < 128) ? s_eid[w][sl]     : __ldg(&g_eid[start + sl]);
        int eid1 = (sl + 1 < 128) ? s_eid[w][sl + 1] : __ldg(&g_eid[start + sl + 1]);
        int sn0 = __ldg(&srcp[eid0]);
        int sn1 = __ldg(&srcp[eid1]);
        float4 c0 = *(const float4*)&g_c[(size_t)eid0 * 128 + lane * 4];
        float4 b0 = *(const float4*)&g_b[(size_t)sn0 * 128 + lane * 4];
        float4 c1 = *(const float4*)&g_c[(size_t)eid1 * 128 + lane * 4];
        float4 b1 = *(const float4*)&g_b[(size_t)sn1 * 128 + lane * 4];

        float m0 = base.x + b0.x + c0.x;
        float m1 = base.y + b0.y + c0.y;
        float m2 = base.z + b0.z + c0.z;
        float m3 = base.w + b0.w + c0.w;
        s.x += m0; s.y += m1; s.z += m2; s.w += m3;
        sq.x = fmaf(m0, m0, sq.x); sq.y = fmaf(m1, m1, sq.y);
        sq.z = fmaf(m2, m2, sq.z); sq.w = fmaf(m3, m3, sq.w);
        mx.x = fmaxf(mx.x, m0); mx.y = fmaxf(mx.y, m1); mx.z = fmaxf(mx.z, m2); mx.w = fmaxf(mx.w, m3);
        mn.x = fminf(mn.x, m0); mn.y = fminf(mn.y, m1); mn.z = fminf(mn.z, m2); mn.w = fminf(mn.w, m3);

        float p0 = base.x + b1.x + c1.x;
        float p1 = base.y + b1.y + c1.y;
        float p2 = base.z + b1.z + c1.z;
        float p3 = base.w + b1.w + c1.w;
        s.x += p0; s.y += p1; s.z += p2; s.w += p3;
        sq.x = fmaf(p0, p0, sq.x); sq.y = fmaf(p1, p1, sq.y);
        sq.z = fmaf(p2, p2, sq.z); sq.w = fmaf(p3, p3, sq.w);
        mx.x = fmaxf(mx.x, p0); mx.y = fmaxf(mx.y, p1); mx.z = fmaxf(mx.z, p2); mx.w = fmaxf(mx.w, p3);
        mn.x = fminf(mn.x, p0); mn.y = fminf(mn.y, p1); mn.z = fminf(mn.z, p2); mn.w = fminf(mn.w, p3);
    }
    for (; sl < deg; sl++) {
        int eid = (sl < 128) ? s_eid[w][sl] : __ldg(&g_eid[start + sl]);
        int sn  = __ldg(&srcp[eid]);
        float4 c = *(const float4*)&g_c[(size_t)eid * 128 + lane * 4];
        float4 b = *(const float4*)&g_b[(size_t)sn * 128 + lane * 4];
        float m0 = base.x + b.x + c.x;
        float m1 = base.y + b.y + c.y;
        float m2 = base.z + b.z + c.z;
        float m3 = base.w + b.w + c.w;
        s.x += m0; s.y += m1; s.z += m2; s.w += m3;
        sq.x = fmaf(m0, m0, sq.x); sq.y = fmaf(m1, m1, sq.y);
        sq.z = fmaf(m2, m2, sq.z); sq.w = fmaf(m3, m3, sq.w);
        mx.x = fmaxf(mx.x, m0); mx.y = fmaxf(mx.y, m1); mx.z = fmaxf(mx.z, m2); mx.w = fmaxf(mx.w, m3);
        mn.x = fminf(mn.x, m0); mn.y = fminf(mn.y, m1); mn.z = fminf(mn.z, m2); mn.w = fminf(mn.w, m3);
    }
    if (deg == 0) {
        mx = make_float4(0.f, 0.f, 0.f, 0.f);
        mn = make_float4(0.f, 0.f, 0.f, 0.f);
    }
    float cs = (float)(deg > 0 ? deg : 1);
    float inv = 1.0f / cs;
    float4 mean = make_float4(s.x * inv, s.y * inv, s.z * inv, s.w * inv);
    float4 msq  = make_float4(sq.x * inv, sq.y * inv, sq.z * inv, sq.w * inv);
    float4 sd;
    sd.x = sqrtf(fmaxf(msq.x - mean.x * mean.x, 0.f) + 1e-5f);
    sd.y = sqrtf(fmaxf(msq.y - mean.y * mean.y, 0.f) + 1e-5f);
    sd.z = sqrtf(fmaxf(msq.z - mean.z * mean.z, 0.f) + 1e-5f);
    sd.w = sqrtf(fmaxf(msq.w - mean.w * mean.w, 0.f) + 1e-5f);

    int t = (lane * 4) >> 5, g0 = (lane * 4) & 31;
    float* aggp = &g_agg[(size_t)n * 512 + t * 128 + g0];
    *(float4*)&aggp[0]  = mean;
    *(float4*)&aggp[32] = mx;
    *(float4*)&aggp[64] = mn;
    *(float4*)&aggp[96] = sd;

    if (lane == 0) {
        float avg = g_avglog;
        float logd = logf((float)deg + 1.0f);
        g_s1[n] = logd / avg;
        g_s2[n] = (deg == 0) ? 1.0f : (avg / logd);
    }
}

// ---------------- post-MLP (tf32 mma) ----------------
__global__ __launch_bounds__(256) void k_post(const float* __restrict__ x,
                                              const float* __restrict__ W_post,
                                              const float* __restrict__ b_post) {
    __shared__ unsigned sA[64 * 36];
    __shared__ uint2    sB0[4 * 4 * 32];
    __shared__ uint2    sB1[4 * 4 * 32];
    __shared__ uint2    sB2[4 * 4 * 32];
    __shared__ uint2    sB3[4 * 4 * 32];
    __shared__ float    s_c1[64], s_c2[64];

    int t  = blockIdx.y;
    int n0 = blockIdx.x * 64;
    int tid = threadIdx.x;
    int wid = tid >> 5, lane = tid & 31;
    int gid = lane >> 2, tig = lane & 3;
    int mt = wid >> 1, nh = wid & 1;
    int m0 = mt * 16;
    const float* Wt = W_post + (size_t)t * 416 * 32;

    for (int i = tid; i < 64 * 8; i += 256) {
        int r = i >> 3, fg = (i & 7) * 4;
        float4 v = *(const float4*)&x[(size_t)(n0 + r) * 128 + t * 32 + fg];
        *(uint4*)&sA[r * 36 + fg] = make_uint4(f2tf(v.x), f2tf(v.y), f2tf(v.z), f2tf(v.w));
    }
    for (int i = tid; i < 512; i += 256) {
        int l = i & 31, nt = (i >> 5) & 3, ks = i >> 7;
        int tg = l & 3, gd = l >> 2;
        int rk = ks * 8 + tg, cn = nt * 8 + gd;
        sB0[i] = make_uint2(f2tf(Wt[rk * 32 + cn]), f2tf(Wt[(rk + 4) * 32 + cn]));
    }
    if (tid < 64) { s_c1[tid] = g_s1[n0 + tid]; s_c2[tid] = g_s2[n0 + tid]; }
    __syncthreads();

    float acc1[2][4], acc2[2][4], acc3[2][4];
#pragma unroll
    for (int nl = 0; nl < 2; nl++)
#pragma unroll
        for (int q = 0; q < 4; q++) { acc1[nl][q] = 0.f; acc2[nl][q] = 0.f; acc3[nl][q] = 0.f; }

#pragma unroll
    for (int ks = 0; ks < 4; ks++) {
        unsigned a0 = sA[(m0 + gid) * 36 + ks * 8 + tig];
        unsigned a1 = sA[(m0 + gid + 8) * 36 + ks * 8 + tig];
        unsigned a2 = sA[(m0 + gid) * 36 + ks * 8 + tig + 4];
        unsigned a3 = sA[(m0 + gid + 8) * 36 + ks * 8 + tig + 4];
#pragma unroll
        for (int nl = 0; nl < 2; nl++) {
            int nt = nh * 2 + nl;
            uint2 b = sB0[(ks * 4 + nt) * 32 + lane];
            mma_tf32(acc1[nl][0], acc1[nl][1], acc1[nl][2], acc1[nl][3],
                     a0, a1, a2, a3, b.x, b.y);
        }
    }

    for (int kt = 0; kt < 4; kt++) {
        int k0 = kt * 32;
        __syncthreads();
        for (int i = tid; i < 64 * 8; i += 256) {
            int r = i >> 3, kg = (i & 7) * 4;
            float4 v = *(const float4*)&g_agg[(size_t)(n0 + r) * 512 + t * 128 + k0 + kg];
            *(uint4*)&sA[r * 36 + kg] = make_uint4(f2tf(v.x), f2tf(v.y), f2tf(v.z), f2tf(v.w));
        }
        for (int i = tid; i < 512; i += 256) {
            int l = i & 31, nt = (i >> 5) & 3, ks = i >> 7;
            int tg = l & 3, gd = l >> 2;
            int rk = k0 + ks * 8 + tg, cn = nt * 8 + gd;
            sB1[i] = make_uint2(f2tf(Wt[(32 + rk) * 32 + cn]),  f2tf(Wt[(32 + rk + 4) * 32 + cn]));
            sB2[i] = make_uint2(f2tf(Wt[(160 + rk) * 32 + cn]), f2tf(Wt[(160 + rk + 4) * 32 + cn]));
            sB3[i] = make_uint2(f2tf(Wt[(288 + rk) * 32 + cn]), f2tf(Wt[(288 + rk + 4) * 32 + cn]));
        }
        __syncthreads();
#pragma unroll
        for (int ks = 0; ks < 4; ks++) {
            unsigned a0 = sA[(m0 + gid) * 36 + ks * 8 + tig];
            unsigned a1 = sA[(m0 + gid + 8) * 36 + ks * 8 + tig];
            unsigned a2 = sA[(m0 + gid) * 36 + ks * 8 + tig + 4];
            unsigned a3 = sA[(m0 + gid + 8) * 36 + ks * 8 + tig + 4];
#pragma unroll
            for (int nl = 0; nl < 2; nl++) {
                int nt = nh * 2 + nl;
                uint2 b1 = sB1[(ks * 4 + nt) * 32 + lane];
                uint2 b2 = sB2[(ks * 4 + nt) * 32 + lane];
                uint2 b3 = sB3[(ks * 4 + nt) * 32 + lane];
                mma_tf32(acc1[nl][0], acc1[nl][1], acc1[nl][2], acc1[nl][3],
                         a0, a1, a2, a3, b1.x, b1.y);
                mma_tf32(acc2[nl][0], acc2[nl][1], acc2[nl][2], acc2[nl][3],
                         a0, a1, a2, a3, b2.x, b2.y);
                mma_tf32(acc3[nl][0], acc3[nl][1], acc3[nl][2], acc3[nl][3],
                         a0, a1, a2, a3, b3.x, b3.y);
            }
        }
    }

#pragma unroll
    for (int nl = 0; nl < 2; nl++) {
        int nt = nh * 2 + nl;
        int col = nt * 8 + tig * 2;
        float bp0 = b_post[t * 32 + col];
        float bp1 = b_post[t * 32 + col + 1];
        int r0 = m0 + gid;
        float c1a = s_c1[r0], c2a = s_c2[r0];
        float y00 = acc1[nl][0] + c1a * acc2[nl][0] + c2a * acc3[nl][0] + bp0;
        float y01 = acc1[nl][1] + c1a * acc2[nl][1] + c2a * acc3[nl][1] + bp1;
        *(float2*)&g_Z[(size_t)(n0 + r0) * 128 + t * 32 + col] = make_float2(y00, y01);
        int r1 = m0 + gid + 8;
        float c1b = s_c1[r1], c2b = s_c2[r1];
        float y10 = acc1[nl][2] + c1b * acc2[nl][2] + c2b * acc3[nl][2] + bp0;
        float y11 = acc1[nl][3] + c1b * acc2[nl][3] + c2b * acc3[nl][3] + bp1;
        *(float2*)&g_Z[(size_t)(n0 + r1) * 128 + t * 32 + col] = make_float2(y10, y11);
    }
}

// ---------------- final (tf32 mma): out = Z @ W_lin^T + b_lin + x ----------------
__global__ __launch_bounds__(256) void k_final(const float* __restrict__ x,
                                               const float* __restrict__ b_lin,
                                               float* __restrict__ out) {
    __shared__ unsigned sA[128 * 36];
    __shared__ uint2    sB[4 * 16 * 32];
    int r0b = blockIdx.x * 128;
    int tid = threadIdx.x;
    int wid = tid >> 5, lane = tid & 31;
    int gid = lane >> 2, tig = lane & 3;
    int m0 = wid * 16;

    float acc[16][4];
#pragma unroll
    for (int nt = 0; nt < 16; nt++)
#pragma unroll
        for (int q = 0; q < 4; q++) acc[nt][q] = 0.f;

    for (int k0 = 0; k0 < 128; k0 += 32) {
        __syncthreads();
        for (int i = tid; i < 128 * 8; i += 256) {
            int r = i >> 3, kg = (i & 7) * 4;
            float4 v = *(const float4*)&g_Z[(size_t)(r0b + r) * 128 + k0 + kg];
            *(uint4*)&sA[r * 36 + kg] = make_uint4(f2tf(v.x), f2tf(v.y), f2tf(v.z), f2tf(v.w));
        }
        for (int i = tid; i < 2048; i += 256) {
            int l = i & 31, nt = (i >> 5) & 15, ks = i >> 9;
            int tg = l & 3, gd = l >> 2;
            int rk = k0 + ks * 8 + tg, cn = nt * 8 + gd;
            sB[i] = make_uint2(f2tf(g_WlinT[rk * 128 + cn]),
                               f2tf(g_WlinT[(rk + 4) * 128 + cn]));
        }
        __syncthreads();
#pragma unroll
        for (int ks = 0; ks < 4; ks++) {
            unsigned a0 = sA[(m0 + gid) * 36 + ks * 8 + tig];
            unsigned a1 = sA[(m0 + gid + 8) * 36 + ks * 8 + tig];
            unsigned a2 = sA[(m0 + gid) * 36 + ks * 8 + tig + 4];
            unsigned a3 = sA[(m0 + gid + 8) * 36 + ks * 8 + tig + 4];
#pragma unroll
            for (int nt = 0; nt < 16; nt++) {
                uint2 b = sB[(ks * 16 + nt) * 32 + lane];
                mma_tf32(acc[nt][0], acc[nt][1], acc[nt][2], acc[nt][3],
                         a0, a1, a2, a3, b.x, b.y);
            }
        }
    }
    int base = r0b + m0;
#pragma unroll
    for (int nt = 0; nt < 16; nt++) {
        int col = nt * 8 + tig * 2;
        float2 bl = *(const float2*)&b_lin[col];
        float2 x0 = *(const float2*)&x[(size_t)(base + gid) * 128 + col];
        float2 x1 = *(const float2*)&x[(size_t)(base + gid + 8) * 128 + col];
        *(float2*)&out[(size_t)(base + gid) * 128 + col] =
            make_float2(acc[nt][0] + bl.x + x0.x, acc[nt][1] + bl.y + x0.y);
        *(float2*)&out[(size_t)(base + gid + 8) * 128 + col] =
            make_float2(acc[nt][2] + bl.x + x1.x, acc[nt][3] + bl.y + x1.y);
    }
}

// ---------------- launch: multi-stream overlap (CSR + ab under egemm/cgemm) ----------------
extern "C" void kernel_launch(void* const* d_in, const int* in_sizes, int n_in,
                              void* d_out, int out_size) {
    const float* x         = (const float*)d_in[0];
    const float* edge_attr = (const float*)d_in[1];
    const int*   edge_idx  = (const int*)d_in[2];
    const float* W_edge    = (const float*)d_in[3];
    const float* b_edge    = (const float*)d_in[4];
    const float* W_pre     = (const float*)d_in[5];
    const float* b_pre     = (const float*)d_in[6];
    const float* W_post    = (const float*)d_in[7];
    const float* b_post    = (const float*)d_in[8];
    const float* W_lin     = (const float*)d_in[9];
    const float* b_lin     = (const float*)d_in[10];
    float* out = (float*)d_out;

    const int* srcp = edge_idx;
    const int* dstp = edge_idx + EE;

    // one-time stream/event setup (first call is outside graph capture)
    static cudaStream_t s1 = 0, s2 = 0;
    static cudaEvent_t ev0 = 0, ev1 = 0, ev2 = 0;
    if (s1 == 0) {
        cudaStreamCreateWithFlags(&s1, cudaStreamNonBlocking);
        cudaStreamCreateWithFlags(&s2, cudaStreamNonBlocking);
        cudaEventCreateWithFlags(&ev0, cudaEventDisableTiming);
        cudaEventCreateWithFlags(&ev1, cudaEventDisableTiming);
        cudaEventCreateWithFlags(&ev2, cudaEventDisableTiming);
    }

    // origin stream (default): zero + prep, then fork point
    k_zero<<<NN / 256, 256>>>();
    k_prep<<<64, 256>>>(W_edge, W_lin, W_pre, b_pre, b_edge);
    cudaEventRecord(ev0, 0);

    // origin: GEMM chain (cgemm is 4th submitted kernel -> profiled next round)
    k_egemm<<<EE / 128, 256>>>(edge_attr);
    k_cgemm<<<EE / 128, 256>>>(W_pre);

    // fork s1: CSR build (independent of GEMMs)
    cudaStreamWaitEvent(s1, ev0, 0);
    k_hist<<<EE / 256, 256, 0, s1>>>(dstp);
    k_scan1<<<256, 256, 0, s1>>>();
    k_scan2<<<1, 256, 0, s1>>>();
    k_scan3<<<256, 256, 0, s1>>>();
    k_scatter<<<EE / 256, 256, 0, s1>>>(dstp);
    cudaEventRecord(ev1, s1);

    // fork s2: node pre-parts (independent of GEMMs and CSR)
    cudaStreamWaitEvent(s2, ev0, 0);
    k_ab<<<(NN * 128) / 256, 256, 0, s2>>>(x, W_pre);
    cudaEventRecord(ev2, s2);

    // join on origin, then the dependent tail
    cudaStreamWaitEvent(0, ev1, 0);
    cudaStreamWaitEvent(0, ev2, 0);
    k_agg<<<NN / 8, 256>>>(srcp);
    k_post<<<dim3(NN / 64, 4), 256>>>(x, W_post, b_post);
    k_final<<<NN / 128, 256>>>(x, b_lin, out);
}

// round 16
// speedup vs baseline: 1.1776x; 1.0534x over previous
#include <cuda_runtime.h>
#include <cuda_bf16.h>
#include <math.h>
#include <stdint.h>
#include <stddef.h>

#define NN 65536
#define EE 1048576
#define FMAXV 3.402823466e38f

// ---------------- static device scratch (no allocations) ----------------
__device__ float g_e[(size_t)EE * 32];      // edge_attr @ W_edge^T
__device__ float g_c[(size_t)EE * 128];     // e @ Wpre_edgepart
__device__ float g_a[(size_t)NN * 128];     // dst-side node pre-part
__device__ float g_b[(size_t)NN * 128];     // src-side node pre-part
__device__ float g_agg[(size_t)NN * 512];   // per node/tower: [mean|mx|mn|std] x32
__device__ float g_Z[(size_t)NN * 128];     // post-MLP output
__device__ float g_s1[NN];
__device__ float g_s2[NN];
__device__ int   g_cnt[NN];
__device__ int   g_fill[NN];
__device__ int   g_rowptr[NN + 1];
__device__ int   g_eid[EE];
__device__ int   g_bsum[256];
__device__ float g_biasm[128];
__device__ float g_WedgeT[128 * 32];        // [k][f]
__device__ float g_WlinT[128 * 128];        // [k][c]
__device__ float g_avglog;

// ---------------- tf32 mma helpers ----------------
__device__ __forceinline__ unsigned f2tf(float x) {
    unsigned r;
    asm("cvt.rna.tf32.f32 %0, %1;" : "=r"(r) : "f"(x));
    return r;
}
__device__ __forceinline__ void mma_tf32(float& d0, float& d1, float& d2, float& d3,
                                         unsigned a0, unsigned a1, unsigned a2, unsigned a3,
                                         unsigned b0, unsigned b1) {
    asm("mma.sync.aligned.m16n8k8.row.col.f32.tf32.tf32.f32 "
        "{%0,%1,%2,%3},{%4,%5,%6,%7},{%8,%9},{%0,%1,%2,%3};"
        : "+f"(d0), "+f"(d1), "+f"(d2), "+f"(d3)
        : "r"(a0), "r"(a1), "r"(a2), "r"(a3), "r"(b0), "r"(b1));
}

// ---------------- setup ----------------
__global__ void k_zero(void) {
    int i = blockIdx.x * 256 + threadIdx.x;
    if (i < NN) { g_cnt[i] = 0; g_fill[i] = 0; }
}

__global__ void k_prep(const float* __restrict__ W_edge, const float* __restrict__ W_lin,
                       const float* __restrict__ W_pre, const float* __restrict__ b_pre,
                       const float* __restrict__ b_edge) {
    int i = blockIdx.x * 256 + threadIdx.x;
    if (i < 128 * 32) {
        int k = i >> 5, f = i & 31;
        g_WedgeT[i] = W_edge[f * 128 + k];
    }
    if (i < 128 * 128) {
        int k = i >> 7, c = i & 127;
        g_WlinT[i] = W_lin[c * 128 + k];
    }
    if (i < 128) {
        int t = i >> 5, g = i & 31;
        float s = b_pre[i];
        for (int j = 0; j < 32; j++)
            s += b_edge[j] * W_pre[t * 3072 + (64 + j) * 32 + g];
        g_biasm[i] = s;
    }
    if (i == 0) {
        const double cnts[6] = {108477.0, 299931.0, 180702.0, 10767.0, 3.0, 2.0};
        double num = 0.0, den = 0.0;
        for (int d = 0; d < 6; d++) { num += cnts[d] * log((double)(d + 1) + 1.0); den += cnts[d]; }
        g_avglog = (float)(num / den);
    }
}

// ---------------- CSR build ----------------
__global__ void k_hist(const int* __restrict__ dst) {
    int i = blockIdx.x * 256 + threadIdx.x;
    if (i < EE) atomicAdd(&g_cnt[dst[i]], 1);
}

__global__ void k_scan1(void) {
    int b = blockIdx.x, t = threadIdx.x;
    int gi = b * 256 + t;
    int v = g_cnt[gi];
    int lane = t & 31, w = t >> 5;
    int incl = v;
#pragma unroll
    for (int off = 1; off < 32; off <<= 1) {
        int u = __shfl_up_sync(0xffffffffu, incl, off);
        if (lane >= off) incl += u;
    }
    __shared__ int wtot[8];
    __shared__ int woff[8];
    if (lane == 31) wtot[w] = incl;
    __syncthreads();
    if (t == 0) {
        int run = 0;
        for (int i = 0; i < 8; i++) { woff[i] = run; run += wtot[i]; }
        g_bsum[b] = run;
    }
    __syncthreads();
    g_rowptr[gi] = woff[w] + incl - v;
}

__global__ void k_scan2(void) {
    int t = threadIdx.x;
    int v = g_bsum[t];
    int lane = t & 31, w = t >> 5;
    int incl = v;
#pragma unroll
    for (int off = 1; off < 32; off <<= 1) {
        int u = __shfl_up_sync(0xffffffffu, incl, off);
        if (lane >= off) incl += u;
    }
    __shared__ int wtot[8];
    __shared__ int woff[8];
    if (lane == 31) wtot[w] = incl;
    __syncthreads();
    if (t == 0) {
        int run = 0;
        for (int i = 0; i < 8; i++) { woff[i] = run; run += wtot[i]; }
    }
    __syncthreads();
    g_bsum[t] = woff[w] + incl - v;
    if (t == 0) g_rowptr[NN] = EE;
}

__global__ void k_scan3(void) {
    int b = blockIdx.x, t = threadIdx.x;
    g_rowptr[b * 256 + t] += g_bsum[b];
}

__global__ void k_scatter(const int* __restrict__ dst) {
    int i = blockIdx.x * 256 + threadIdx.x;
    if (i < EE) {
        int d = dst[i];
        int slot = g_rowptr[d] + atomicAdd(&g_fill[d], 1);
        g_eid[slot] = i;
    }
}

// ---------------- node pre-parts (__ldg: L1-resident weights) ----------------
__global__ void k_ab(const float* __restrict__ x, const float* __restrict__ W_pre) {
    int i = blockIdx.x * 256 + threadIdx.x;
    if (i >= NN * 128) return;
    int n = i >> 7, ch = i & 127;
    int t = ch >> 5, g = ch & 31;
    const float* xr = x + (size_t)n * 128 + t * 32;
    const float* wa = W_pre + t * 3072 + g;
    const float* wb = wa + 1024;
    float a = 0.f, b = 0.f;
#pragma unroll
    for (int f = 0; f < 32; f++) {
        float xv = __ldg(&xr[f]);
        a = fmaf(xv, __ldg(&wa[f * 32]), a);
        b = fmaf(xv, __ldg(&wb[f * 32]), b);
    }
    g_a[i] = a; g_b[i] = b;
}

// ---------------- e-GEMM (tf32 mma, cp.async double-buffered) ----------------
__global__ __launch_bounds__(256) void k_egemm(const float* __restrict__ ea) {
    __shared__ float sA[2][128 * 20];
    __shared__ uint2 sB[16 * 4 * 32];
    int r0b = blockIdx.x * 128;
    int tid = threadIdx.x;
    int wid = tid >> 5, lane = tid & 31;
    int gid = lane >> 2, tig = lane & 3;
    int m0 = wid * 16;

    for (int i = tid; i < 2048; i += 256) {
        int l = i & 31, nt = (i >> 5) & 3, gks = i >> 7;
        int tg = l & 3, gd = l >> 2;
        int rk = gks * 8 + tg, cn = nt * 8 + gd;
        sB[i] = make_uint2(f2tf(g_WedgeT[rk * 32 + cn]),
                           f2tf(g_WedgeT[(rk + 4) * 32 + cn]));
    }

    #define EG_COPY(kc, buf) do {                                                   \
        for (int i = tid; i < 512; i += 256) {                                      \
            int r = i >> 2, kg = (i & 3) * 4;                                       \
            const float* src = &ea[(size_t)(r0b + r) * 128 + (kc) * 16 + kg];       \
            unsigned daddr = (unsigned)__cvta_generic_to_shared(&sA[buf][r * 20 + kg]); \
            asm volatile("cp.async.cg.shared.global [%0], [%1], 16;" :: "r"(daddr), "l"(src)); \
        }                                                                           \
        asm volatile("cp.async.commit_group;");                                     \
    } while (0)

    float acc[4][4];
#pragma unroll
    for (int nt = 0; nt < 4; nt++)
#pragma unroll
        for (int q = 0; q < 4; q++) acc[nt][q] = 0.f;

    EG_COPY(0, 0);
    for (int kc = 0; kc < 8; kc++) {
        int buf = kc & 1;
        if (kc < 7) {
            EG_COPY(kc + 1, buf ^ 1);
            asm volatile("cp.async.wait_group 1;");
        } else {
            asm volatile("cp.async.wait_group 0;");
        }
        __syncthreads();
#pragma unroll
        for (int ks = 0; ks < 2; ks++) {
            const float* Ab = &sA[buf][0];
            unsigned a0 = f2tf(Ab[(m0 + gid) * 20 + ks * 8 + tig]);
            unsigned a1 = f2tf(Ab[(m0 + gid + 8) * 20 + ks * 8 + tig]);
            unsigned a2 = f2tf(Ab[(m0 + gid) * 20 + ks * 8 + tig + 4]);
            unsigned a3 = f2tf(Ab[(m0 + gid + 8) * 20 + ks * 8 + tig + 4]);
            int gks = kc * 2 + ks;
#pragma unroll
            for (int nt = 0; nt < 4; nt++) {
                uint2 b = sB[(gks * 4 + nt) * 32 + lane];
                mma_tf32(acc[nt][0], acc[nt][1], acc[nt][2], acc[nt][3],
                         a0, a1, a2, a3, b.x, b.y);
            }
        }
        __syncthreads();
    }
    #undef EG_COPY

    int base = r0b + m0;
#pragma unroll
    for (int nt = 0; nt < 4; nt++) {
        int col = nt * 8 + tig * 2;
        *(float2*)&g_e[(size_t)(base + gid) * 32 + col] = make_float2(acc[nt][0], acc[nt][1]);
        *(float2*)&g_e[(size_t)(base + gid + 8) * 32 + col] = make_float2(acc[nt][2], acc[nt][3]);
    }
}

// ---------------- c-GEMM (tf32 mma, 512 threads, col-split warps) ----------------
// 128 rows/block, 16 warps = 8 row-groups x 2 col-halves; each warp 16 rows x 64 cols
// (8 n-tiles, 32 acc regs) -> ~60 regs/thread -> 2 blocks/SM (32 warps).
__global__ __launch_bounds__(512) void k_cgemm(const float* __restrict__ W_pre) {
    __shared__ unsigned sE[128 * 36];
    __shared__ uint2    sB[4 * 16 * 32];
    int r0b = blockIdx.x * 128;
    int tid = threadIdx.x;
    int wid = tid >> 5, lane = tid & 31;
    int gid = lane >> 2, tig = lane & 3;
    int mt = wid >> 1, nh = wid & 1;
    int m0 = mt * 16;

    for (int i = tid; i < 128 * 8; i += 512) {
        int r = i >> 3, kg = (i & 7) * 4;
        float4 v = *(const float4*)&g_e[(size_t)(r0b + r) * 32 + kg];
        *(uint4*)&sE[r * 36 + kg] = make_uint4(f2tf(v.x), f2tf(v.y), f2tf(v.z), f2tf(v.w));
    }
    for (int i = tid; i < 2048; i += 512) {
        int l = i & 31, nt = (i >> 5) & 15, ks = i >> 9;
        int tg = l & 3, gd = l >> 2;
        int j = ks * 8 + tg;
        int o = nt * 8 + gd;
        int t = o >> 5, g = o & 31;
        sB[i] = make_uint2(f2tf(W_pre[t * 3072 + (64 + j) * 32 + g]),
                           f2tf(W_pre[t * 3072 + (64 + j + 4) * 32 + g]));
    }
    __syncthreads();

    float acc[8][4];
#pragma unroll
    for (int nl = 0; nl < 8; nl++)
#pragma unroll
        for (int q = 0; q < 4; q++) acc[nl][q] = 0.f;

#pragma unroll
    for (int ks = 0; ks < 4; ks++) {
        unsigned a0 = sE[(m0 + gid) * 36 + ks * 8 + tig];
        unsigned a1 = sE[(m0 + gid + 8) * 36 + ks * 8 + tig];
        unsigned a2 = sE[(m0 + gid) * 36 + ks * 8 + tig + 4];
        unsigned a3 = sE[(m0 + gid + 8) * 36 + ks * 8 + tig + 4];
#pragma unroll
        for (int nl = 0; nl < 8; nl++) {
            int nt = nh * 8 + nl;
            uint2 b = sB[(ks * 16 + nt) * 32 + lane];
            mma_tf32(acc[nl][0], acc[nl][1], acc[nl][2], acc[nl][3],
                     a0, a1, a2, a3, b.x, b.y);
        }
    }
    int base = r0b + m0;
#pragma unroll
    for (int nl = 0; nl < 8; nl++) {
        int col = (nh * 8 + nl) * 8 + tig * 2;
        *(float2*)&g_c[(size_t)(base + gid) * 128 + col] = make_float2(acc[nl][0], acc[nl][1]);
        *(float2*)&g_c[(size_t)(base + gid + 8) * 128 + col] = make_float2(acc[nl][2], acc[nl][3]);
    }
}

// ---------------- aggregation: one warp per node (sorted edge list, 2-edge ILP) ----------------
__global__ __launch_bounds__(256) void k_agg(const int* __restrict__ srcp) {
    __shared__ int s_eid[8][128];
    int w = threadIdx.x >> 5;
    int lane = threadIdx.x & 31;
    int n = blockIdx.x * 8 + w;
    if (n >= NN) return;
    int start = g_rowptr[n], end = g_rowptr[n + 1];
    int deg = end - start;
    int msort = deg < 128 ? deg : 128;

    for (int j = lane; j < msort; j += 32) s_eid[w][j] = g_eid[start + j];
    __syncwarp();
    for (int pass = 0; pass < msort; pass++) {
        int off = pass & 1;
        for (int j = lane; 2 * j + 1 + off < msort; j += 32) {
            int i0 = 2 * j + off, i1 = i0 + 1;
            int a = s_eid[w][i0], b = s_eid[w][i1];
            if (a > b) { s_eid[w][i0] = b; s_eid[w][i1] = a; }
        }
        __syncwarp();
    }

    float4 base = *(const float4*)&g_a[(size_t)n * 128 + lane * 4];
    float4 bm   = *(const float4*)&g_biasm[lane * 4];
    base.x += bm.x; base.y += bm.y; base.z += bm.z; base.w += bm.w;

    float4 s  = make_float4(0.f, 0.f, 0.f, 0.f);
    float4 sq = make_float4(0.f, 0.f, 0.f, 0.f);
    float4 mx = make_float4(-FMAXV, -FMAXV, -FMAXV, -FMAXV);
    float4 mn = make_float4( FMAXV,  FMAXV,  FMAXV,  FMAXV);

    int sl = 0;
    for (; sl + 2 <= deg; sl += 2) {
        int eid0 = (sl     < 128) ? s_eid[w][sl]     : __ldg(&g_eid[start + sl]);
        int eid1 = (sl + 1 < 128) ? s_eid[w][sl + 1] : __ldg(&g_eid[start + sl + 1]);
        int sn0 = __ldg(&srcp[eid0]);
        int sn1 = __ldg(&srcp[eid1]);
        float4 c0 = *(const float4*)&g_c[(size_t)eid0 * 128 + lane * 4];
        float4 b0 = *(const float4*)&g_b[(size_t)sn0 * 128 + lane * 4];
        float4 c1 = *(const float4*)&g_c[(size_t)eid1 * 128 + lane * 4];
        float4 b1 = *(const float4*)&g_b[(size_t)sn1 * 128 + lane * 4];

        float m0 = base.x + b0.x + c0.x;
        float m1 = base.y + b0.y + c0.y;
        float m2 = base.z + b0.z + c0.z;
        float m3 = base.w + b0.w + c0.w;
        s.x += m0; s.y += m1; s.z += m2; s.w += m3;
        sq.x = fmaf(m0, m0, sq.x); sq.y = fmaf(m1, m1, sq.y);
        sq.z = fmaf(m2, m2, sq.z); sq.w = fmaf(m3, m3, sq.w);
        mx.x = fmaxf(mx.x, m0); mx.y = fmaxf(mx.y, m1); mx.z = fmaxf(mx.z, m2); mx.w = fmaxf(mx.w, m3);
        mn.x = fminf(mn.x, m0); mn.y = fminf(mn.y, m1); mn.z = fminf(mn.z, m2); mn.w = fminf(mn.w, m3);

        float p0 = base.x + b1.x + c1.x;
        float p1 = base.y + b1.y + c1.y;
        float p2 = base.z + b1.z + c1.z;
        float p3 = base.w + b1.w + c1.w;
        s.x += p0; s.y += p1; s.z += p2; s.w += p3;
        sq.x = fmaf(p0, p0, sq.x); sq.y = fmaf(p1, p1, sq.y);
        sq.z = fmaf(p2, p2, sq.z); sq.w = fmaf(p3, p3, sq.w);
        mx.x = fmaxf(mx.x, p0); mx.y = fmaxf(mx.y, p1); mx.z = fmaxf(mx.z, p2); mx.w = fmaxf(mx.w, p3);
        mn.x = fminf(mn.x, p0); mn.y = fminf(mn.y, p1); mn.z = fminf(mn.z, p2); mn.w = fminf(mn.w, p3);
    }
    for (; sl < deg; sl++) {
        int eid = (sl < 128) ? s_eid[w][sl] : __ldg(&g_eid[start + sl]);
        int sn  = __ldg(&srcp[eid]);
        float4 c = *(const float4*)&g_c[(size_t)eid * 128 + lane * 4];
        float4 b = *(const float4*)&g_b[(size_t)sn * 128 + lane * 4];
        float m0 = base.x + b.x + c.x;
        float m1 = base.y + b.y + c.y;
        float m2 = base.z + b.z + c.z;
        float m3 = base.w + b.w + c.w;
        s.x += m0; s.y += m1; s.z += m2; s.w += m3;
        sq.x = fmaf(m0, m0, sq.x); sq.y = fmaf(m1, m1, sq.y);
        sq.z = fmaf(m2, m2, sq.z); sq.w = fmaf(m3, m3, sq.w);
        mx.x = fmaxf(mx.x, m0); mx.y = fmaxf(mx.y, m1); mx.z = fmaxf(mx.z, m2); mx.w = fmaxf(mx.w, m3);
        mn.x = fminf(mn.x, m0); mn.y = fminf(mn.y, m1); mn.z = fminf(mn.z, m2); mn.w = fminf(mn.w, m3);
    }
    if (deg == 0) {
        mx = make_float4(0.f, 0.f, 0.f, 0.f);
        mn = make_float4(0.f, 0.f, 0.f, 0.f);
    }
    float cs = (float)(deg > 0 ? deg : 1);
    float inv = 1.0f / cs;
    float4 mean = make_float4(s.x * inv, s.y * inv, s.z * inv, s.w * inv);
    float4 msq  = make_float4(sq.x * inv, sq.y * inv, sq.z * inv, sq.w * inv);
    float4 sd;
    sd.x = sqrtf(fmaxf(msq.x - mean.x * mean.x, 0.f) + 1e-5f);
    sd.y = sqrtf(fmaxf(msq.y - mean.y * mean.y, 0.f) + 1e-5f);
    sd.z = sqrtf(fmaxf(msq.z - mean.z * mean.z, 0.f) + 1e-5f);
    sd.w = sqrtf(fmaxf(msq.w - mean.w * mean.w, 0.f) + 1e-5f);

    int t = (lane * 4) >> 5, g0 = (lane * 4) & 31;
    float* aggp = &g_agg[(size_t)n * 512 + t * 128 + g0];
    *(float4*)&aggp[0]  = mean;
    *(float4*)&aggp[32] = mx;
    *(float4*)&aggp[64] = mn;
    *(float4*)&aggp[96] = sd;

    if (lane == 0) {
        float avg = g_avglog;
        float logd = logf((float)deg + 1.0f);
        g_s1[n] = logd / avg;
        g_s2[n] = (deg == 0) ? 1.0f : (avg / logd);
    }
}

// ---------------- post-MLP (tf32 mma) ----------------
__global__ __launch_bounds__(256) void k_post(const float* __restrict__ x,
                                              const float* __restrict__ W_post,
                                              const float* __restrict__ b_post) {
    __shared__ unsigned sA[64 * 36];
    __shared__ uint2    sB0[4 * 4 * 32];
    __shared__ uint2    sB1[4 * 4 * 32];
    __shared__ uint2    sB2[4 * 4 * 32];
    __shared__ uint2    sB3[4 * 4 * 32];
    __shared__ float    s_c1[64], s_c2[64];

    int t  = blockIdx.y;
    int n0 = blockIdx.x * 64;
    int tid = threadIdx.x;
    int wid = tid >> 5, lane = tid & 31;
    int gid = lane >> 2, tig = lane & 3;
    int mt = wid >> 1, nh = wid & 1;
    int m0 = mt * 16;
    const float* Wt = W_post + (size_t)t * 416 * 32;

    for (int i = tid; i < 64 * 8; i += 256) {
        int r = i >> 3, fg = (i & 7) * 4;
        float4 v = *(const float4*)&x[(size_t)(n0 + r) * 128 + t * 32 + fg];
        *(uint4*)&sA[r * 36 + fg] = make_uint4(f2tf(v.x), f2tf(v.y), f2tf(v.z), f2tf(v.w));
    }
    for (int i = tid; i < 512; i += 256) {
        int l = i & 31, nt = (i >> 5) & 3, ks = i >> 7;
        int tg = l & 3, gd = l >> 2;
        int rk = ks * 8 + tg, cn = nt * 8 + gd;
        sB0[i] = make_uint2(f2tf(Wt[rk * 32 + cn]), f2tf(Wt[(rk + 4) * 32 + cn]));
    }
    if (tid < 64) { s_c1[tid] = g_s1[n0 + tid]; s_c2[tid] = g_s2[n0 + tid]; }
    __syncthreads();

    float acc1[2][4], acc2[2][4], acc3[2][4];
#pragma unroll
    for (int nl = 0; nl < 2; nl++)
#pragma unroll
        for (int q = 0; q < 4; q++) { acc1[nl][q] = 0.f; acc2[nl][q] = 0.f; acc3[nl][q] = 0.f; }

#pragma unroll
    for (int ks = 0; ks < 4; ks++) {
        unsigned a0 = sA[(m0 + gid) * 36 + ks * 8 + tig];
        unsigned a1 = sA[(m0 + gid + 8) * 36 + ks * 8 + tig];
        unsigned a2 = sA[(m0 + gid) * 36 + ks * 8 + tig + 4];
        unsigned a3 = sA[(m0 + gid + 8) * 36 + ks * 8 + tig + 4];
#pragma unroll
        for (int nl = 0; nl < 2; nl++) {
            int nt = nh * 2 + nl;
            uint2 b = sB0[(ks * 4 + nt) * 32 + lane];
            mma_tf32(acc1[nl][0], acc1[nl][1], acc1[nl][2], acc1[nl][3],
                     a0, a1, a2, a3, b.x, b.y);
        }
    }

    for (int kt = 0; kt < 4; kt++) {
        int k0 = kt * 32;
        __syncthreads();
        for (int i = tid; i < 64 * 8; i += 256) {
            int r = i >> 3, kg = (i & 7) * 4;
            float4 v = *(const float4*)&g_agg[(size_t)(n0 + r) * 512 + t * 128 + k0 + kg];
            *(uint4*)&sA[r * 36 + kg] = make_uint4(f2tf(v.x), f2tf(v.y), f2tf(v.z), f2tf(v.w));
        }
        for (int i = tid; i < 512; i += 256) {
            int l = i & 31, nt = (i >> 5) & 3, ks = i >> 7;
            int tg = l & 3, gd = l >> 2;
            int rk = k0 + ks * 8 + tg, cn = nt * 8 + gd;
            sB1[i] = make_uint2(f2tf(Wt[(32 + rk) * 32 + cn]),  f2tf(Wt[(32 + rk + 4) * 32 + cn]));
            sB2[i] = make_uint2(f2tf(Wt[(160 + rk) * 32 + cn]), f2tf(Wt[(160 + rk + 4) * 32 + cn]));
            sB3[i] = make_uint2(f2tf(Wt[(288 + rk) * 32 + cn]), f2tf(Wt[(288 + rk + 4) * 32 + cn]));
        }
        __syncthreads();
#pragma unroll
        for (int ks = 0; ks < 4; ks++) {
            unsigned a0 = sA[(m0 + gid) * 36 + ks * 8 + tig];
            unsigned a1 = sA[(m0 + gid + 8) * 36 + ks * 8 + tig];
            unsigned a2 = sA[(m0 + gid) * 36 + ks * 8 + tig + 4];
            unsigned a3 = sA[(m0 + gid + 8) * 36 + ks * 8 + tig + 4];
#pragma unroll
            for (int nl = 0; nl < 2; nl++) {
                int nt = nh * 2 + nl;
                uint2 b1 = sB1[(ks * 4 + nt) * 32 + lane];
                uint2 b2 = sB2[(ks * 4 + nt) * 32 + lane];
                uint2 b3 = sB3[(ks * 4 + nt) * 32 + lane];
                mma_tf32(acc1[nl][0], acc1[nl][1], acc1[nl][2], acc1[nl][3],
                         a0, a1, a2, a3, b1.x, b1.y);
                mma_tf32(acc2[nl][0], acc2[nl][1], acc2[nl][2], acc2[nl][3],
                         a0, a1, a2, a3, b2.x, b2.y);
                mma_tf32(acc3[nl][0], acc3[nl][1], acc3[nl][2], acc3[nl][3],
                         a0, a1, a2, a3, b3.x, b3.y);
            }
        }
    }

#pragma unroll
    for (int nl = 0; nl < 2; nl++) {
        int nt = nh * 2 + nl;
        int col = nt * 8 + tig * 2;
        float bp0 = b_post[t * 32 + col];
        float bp1 = b_post[t * 32 + col + 1];
        int r0 = m0 + gid;
        float c1a = s_c1[r0], c2a = s_c2[r0];
        float y00 = acc1[nl][0] + c1a * acc2[nl][0] + c2a * acc3[nl][0] + bp0;
        float y01 = acc1[nl][1] + c1a * acc2[nl][1] + c2a * acc3[nl][1] + bp1;
        *(float2*)&g_Z[(size_t)(n0 + r0) * 128 + t * 32 + col] = make_float2(y00, y01);
        int r1 = m0 + gid + 8;
        float c1b = s_c1[r1], c2b = s_c2[r1];
        float y10 = acc1[nl][2] + c1b * acc2[nl][2] + c2b * acc3[nl][2] + bp0;
        float y11 = acc1[nl][3] + c1b * acc2[nl][3] + c2b * acc3[nl][3] + bp1;
        *(float2*)&g_Z[(size_t)(n0 + r1) * 128 + t * 32 + col] = make_float2(y10, y11);
    }
}

// ---------------- final (tf32 mma): out = Z @ W_lin^T + b_lin + x ----------------
__global__ __launch_bounds__(256) void k_final(const float* __restrict__ x,
                                               const float* __restrict__ b_lin,
                                               float* __restrict__ out) {
    __shared__ unsigned sA[128 * 36];
    __shared__ uint2    sB[4 * 16 * 32];
    int r0b = blockIdx.x * 128;
    int tid = threadIdx.x;
    int wid = tid >> 5, lane = tid & 31;
    int gid = lane >> 2, tig = lane & 3;
    int m0 = wid * 16;

    float acc[16][4];
#pragma unroll
    for (int nt = 0; nt < 16; nt++)
#pragma unroll
        for (int q = 0; q < 4; q++) acc[nt][q] = 0.f;

    for (int k0 = 0; k0 < 128; k0 += 32) {
        __syncthreads();
        for (int i = tid; i < 128 * 8; i += 256) {
            int r = i >> 3, kg = (i & 7) * 4;
            float4 v = *(const float4*)&g_Z[(size_t)(r0b + r) * 128 + k0 + kg];
            *(uint4*)&sA[r * 36 + kg] = make_uint4(f2tf(v.x), f2tf(v.y), f2tf(v.z), f2tf(v.w));
        }
        for (int i = tid; i < 2048; i += 256) {
            int l = i & 31, nt = (i >> 5) & 15, ks = i >> 9;
            int tg = l & 3, gd = l >> 2;
            int rk = k0 + ks * 8 + tg, cn = nt * 8 + gd;
            sB[i] = make_uint2(f2tf(g_WlinT[rk * 128 + cn]),
                               f2tf(g_WlinT[(rk + 4) * 128 + cn]));
        }
        __syncthreads();
#pragma unroll
        for (int ks = 0; ks < 4; ks++) {
            unsigned a0 = sA[(m0 + gid) * 36 + ks * 8 + tig];
            unsigned a1 = sA[(m0 + gid + 8) * 36 + ks * 8 + tig];
            unsigned a2 = sA[(m0 + gid) * 36 + ks * 8 + tig + 4];
            unsigned a3 = sA[(m0 + gid + 8) * 36 + ks * 8 + tig + 4];
#pragma unroll
            for (int nt = 0; nt < 16; nt++) {
                uint2 b = sB[(ks * 16 + nt) * 32 + lane];
                mma_tf32(acc[nt][0], acc[nt][1], acc[nt][2], acc[nt][3],
                         a0, a1, a2, a3, b.x, b.y);
            }
        }
    }
    int base = r0b + m0;
#pragma unroll
    for (int nt = 0; nt < 16; nt++) {
        int col = nt * 8 + tig * 2;
        float2 bl = *(const float2*)&b_lin[col];
        float2 x0 = *(const float2*)&x[(size_t)(base + gid) * 128 + col];
        float2 x1 = *(const float2*)&x[(size_t)(base + gid + 8) * 128 + col];
        *(float2*)&out[(size_t)(base + gid) * 128 + col] =
            make_float2(acc[nt][0] + bl.x + x0.x, acc[nt][1] + bl.y + x0.y);
        *(float2*)&out[(size_t)(base + gid + 8) * 128 + col] =
            make_float2(acc[nt][2] + bl.x + x1.x, acc[nt][3] + bl.y + x1.y);
    }
}

// ---------------- launch: multi-stream overlap (CSR + ab under egemm/cgemm) ----------------
extern "C" void kernel_launch(void* const* d_in, const int* in_sizes, int n_in,
                              void* d_out, int out_size) {
    const float* x         = (const float*)d_in[0];
    const float* edge_attr = (const float*)d_in[1];
    const int*   edge_idx  = (const int*)d_in[2];
    const float* W_edge    = (const float*)d_in[3];
    const float* b_edge    = (const float*)d_in[4];
    const float* W_pre     = (const float*)d_in[5];
    const float* b_pre     = (const float*)d_in[6];
    const float* W_post    = (const float*)d_in[7];
    const float* b_post    = (const float*)d_in[8];
    const float* W_lin     = (const float*)d_in[9];
    const float* b_lin     = (const float*)d_in[10];
    float* out = (float*)d_out;

    const int* srcp = edge_idx;
    const int* dstp = edge_idx + EE;

    static cudaStream_t s1 = 0, s2 = 0;
    static cudaEvent_t ev0 = 0, ev1 = 0, ev2 = 0;
    if (s1 == 0) {
        cudaStreamCreateWithFlags(&s1, cudaStreamNonBlocking);
        cudaStreamCreateWithFlags(&s2, cudaStreamNonBlocking);
        cudaEventCreateWithFlags(&ev0, cudaEventDisableTiming);
        cudaEventCreateWithFlags(&ev1, cudaEventDisableTiming);
        cudaEventCreateWithFlags(&ev2, cudaEventDisableTiming);
    }

    k_zero<<<NN / 256, 256>>>();
    k_prep<<<64, 256>>>(W_edge, W_lin, W_pre, b_pre, b_edge);
    cudaEventRecord(ev0, 0);

    k_egemm<<<EE / 128, 256>>>(edge_attr);
    k_cgemm<<<EE / 128, 512>>>(W_pre);           // profiled slot (4th submission)

    cudaStreamWaitEvent(s1, ev0, 0);
    k_hist<<<EE / 256, 256, 0, s1>>>(dstp);
    k_scan1<<<256, 256, 0, s1>>>();
    k_scan2<<<1, 256, 0, s1>>>();
    k_scan3<<<256, 256, 0, s1>>>();
    k_scatter<<<EE / 256, 256, 0, s1>>>(dstp);
    cudaEventRecord(ev1, s1);

    cudaStreamWaitEvent(s2, ev0, 0);
    k_ab<<<(NN * 128) / 256, 256, 0, s2>>>(x, W_pre);
    cudaEventRecord(ev2, s2);

    cudaStreamWaitEvent(0, ev1, 0);
    cudaStreamWaitEvent(0, ev2, 0);
    k_agg<<<NN / 8, 256>>>(srcp);
    k_post<<<dim3(NN / 64, 4), 256>>>(x, W_post, b_post);
    k_final<<<NN / 128, 256>>>(x, b_lin, out);
}